// round 7
// baseline (speedup 1.0000x reference)
#include <cuda_runtime.h>
#include <math.h>
#include <stdint.h>

// ---------------- problem constants ----------------
#define Bc     8
#define Tc     2048
#define VDIMc  1024
#define ADIMc  768
#define DMc    256
#define HIDc   1024
#define MROWS  (Bc * Tc)          // 16384
#define XDIM   (3 * DMc)          // 768

// quantization: x ~= (128*x1 + x0) * range / 16256
#define QMAX   16256.0f
#define INVR_ACT  2032.0f         // range 8   (video/audio)
#define INVR_X    16256.0f        // range 1   (features)
#define INVR_W    65024.0f        // range 0.25 (weights)

// ---------------- scratch (device globals; no allocation allowed) ----------------
__device__ float g_v   [MROWS * DMc];
__device__ float g_a   [MROWS * DMc];
__device__ float g_actx[MROWS * DMc];
__device__ float g_part[MROWS * 8];

__device__ int8_t g_V1[(size_t)MROWS * VDIMc];
__device__ int8_t g_V0[(size_t)MROWS * VDIMc];
__device__ int8_t g_A1[(size_t)MROWS * ADIMc];
__device__ int8_t g_A0[(size_t)MROWS * ADIMc];
__device__ int8_t g_X1[(size_t)MROWS * XDIM];
__device__ int8_t g_X0[(size_t)MROWS * XDIM];
__device__ int8_t g_Bv[DMc  * 4 * VDIMc];   // [b1|b0|b1|b0] per row, [N,4K]
__device__ int8_t g_Ba[DMc  * 4 * ADIMc];
__device__ int8_t g_B1[HIDc * 4 * XDIM];

// ---------------- helpers ----------------
__device__ __forceinline__ uint32_t smem_u32(const void* p) {
    uint32_t a;
    asm("{ .reg .u64 t; cvta.to.shared.u64 t, %1; cvt.u32.u64 %0, t; }" : "=r"(a) : "l"(p));
    return a;
}
__device__ __forceinline__ float gelu_exact(float h) {
    return 0.5f * h * (1.f + erff(h * 0.70710678118654752f));
}
__device__ __forceinline__ void quant2(float x, float invr, int& hi, int& lo) {
    int q = __float2int_rn(fminf(fmaxf(x * invr, -QMAX), QMAX));
    hi = (q + 64) >> 7;          // [-127,127]
    lo = q - (hi << 7);          // [-64,63]
}

#define LDSM4(rg, addr) \
    asm volatile("ldmatrix.sync.aligned.m8n8.x4.shared.b16 {%0,%1,%2,%3}, [%4];" \
        : "=r"((rg)[0]), "=r"((rg)[1]), "=r"((rg)[2]), "=r"((rg)[3]) : "r"(addr))

#define MMAS8(d, a, b) \
    asm volatile("mma.sync.aligned.m16n8k32.row.col.s32.s8.s8.s32 " \
        "{%0,%1,%2,%3}, {%4,%5,%6,%7}, {%8,%9}, {%0,%1,%2,%3};" \
        : "+r"((d)[0]), "+r"((d)[1]), "+r"((d)[2]), "+r"((d)[3]) \
        : "r"((a)[0]), "r"((a)[1]), "r"((a)[2]), "r"((a)[3]), "r"((b)[0]), "r"((b)[1]))

#define CP_ASYNC16(dst, src) \
    asm volatile("cp.async.cg.shared.global [%0], [%1], 16;" :: "r"(dst), "l"(src) : "memory")
#define CP_COMMIT() asm volatile("cp.async.commit_group;" ::: "memory")
#define CP_WAIT1()  asm volatile("cp.async.wait_group 1;" ::: "memory")

// smem tile: 128 rows x 64 bytes, XOR swizzle on 16B groups
__device__ __forceinline__ uint32_t sw_off(int r, int c16) {
    return (uint32_t)(((r << 6) + (c16 << 4)) ^ ((r & 3) << 4));
}

// ---------------- int8 split GEMM ----------------
// C = range-scaled [A1|A1|A0|A0] @ [B1|B0|B1|B0]^T, region weights 2^14,2^7,2^7,1
#define STAGES 3
#define TILEB  16384
static constexpr int SM_EPI    = STAGES * TILEB;     // 49152
static constexpr int GSM_TOTAL = SM_EPI + 1536;

template <bool FUSE>
__global__ void __launch_bounds__(256, 2)
i8_gemm(const int8_t* __restrict__ A1p, const int8_t* __restrict__ A0p,
        const int8_t* __restrict__ Bm,
        const float* __restrict__ bias, const float* __restrict__ W2,
        float* __restrict__ out, int K, int Ntot, float fscale)
{
    extern __shared__ char smem[];
    const uint32_t sbase = smem_u32(smem);
    const int tid  = threadIdx.x;
    const int lane = tid & 31, warp = tid >> 5;
    const int wm = warp >> 2, wn = warp & 3;          // 2 x 4 warp grid (64m x 32n)
    const int bx = blockIdx.x, by = blockIdx.y;

    float* sBias = (float*)(smem + SM_EPI);
    float* sW2   = (float*)(smem + SM_EPI + 512);
    float* sRow  = (float*)(smem + SM_EPI + 1024);
    if (tid < 128) {
        sBias[tid] = bias[bx * 128 + tid];
        if (FUSE) { sW2[tid] = W2[bx * 128 + tid]; sRow[tid] = 0.f; }
    }

    const int ntK = K >> 6;           // 64 int8 per chunk row
    const int nt  = 4 * ntK;
    const int K4  = 4 * K;

    const int cr = tid >> 2, cc = tid & 3;

    const int8_t* A1b = A1p + (size_t)(by * 128 + cr) * K + cc * 16;
    const int8_t* A0b = A0p + (size_t)(by * 128 + cr) * K + cc * 16;
    const int8_t* Bb  = Bm  + (size_t)(bx * 128 + cr) * K4 + cc * 16;

    int   iacc[4][4][4];
    float facc[4][4][4];
#pragma unroll
    for (int i = 0; i < 4; i++)
#pragma unroll
        for (int j = 0; j < 4; j++)
#pragma unroll
            for (int q = 0; q < 4; q++) { iacc[i][j][q] = 0; facc[i][j][q] = 0.f; }

    auto load_tile = [&](int stage, int kt) {
        const uint32_t sA = sbase + stage * TILEB;
        const uint32_t sB = sA + 8192;
        const int reg = kt / ntK;
        const int klocal = kt - reg * ntK;
        const int8_t* a0 = ((reg < 2) ? A1b : A0b) + klocal * 64;
        const int8_t* b0 = Bb + kt * 64;
        CP_ASYNC16(sA + sw_off(cr,      cc), a0);
        CP_ASYNC16(sA + sw_off(cr + 64, cc), a0 + (size_t)64 * K);
        CP_ASYNC16(sB + sw_off(cr,      cc), b0);
        CP_ASYNC16(sB + sw_off(cr + 64, cc), b0 + (size_t)64 * K4);
    };

    load_tile(0, 0); CP_COMMIT();
    load_tile(1, 1); CP_COMMIT();

    const int arow  = wm * 64 + (lane & 15);
    const int acsel = lane >> 4;
    const int brow  = wn * 32 + (lane & 7) + ((lane >> 4) << 3);
    const int bcsel = (lane >> 3) & 1;

    for (int kt = 0; kt < nt; kt++) {
        // fold s32 -> f32 at region-weight boundaries (regions 1,2 share 2^7)
        if (kt == ntK || kt == 3 * ntK) {
            const float w = (kt == ntK) ? 16384.f : 128.f;
#pragma unroll
            for (int i = 0; i < 4; i++)
#pragma unroll
                for (int j = 0; j < 4; j++)
#pragma unroll
                    for (int q = 0; q < 4; q++) {
                        facc[i][j][q] += w * (float)iacc[i][j][q];
                        iacc[i][j][q] = 0;
                    }
        }

        CP_WAIT1();
        __syncthreads();

        const int nk = kt + 2;
        if (nk < nt) load_tile(nk % STAGES, nk);
        CP_COMMIT();

        const uint32_t sA = sbase + (kt % STAGES) * TILEB;
        const uint32_t sB = sA + 8192;
#pragma unroll
        for (int ks = 0; ks < 2; ks++) {
            uint32_t afr[4][4], bfr[2][4];
#pragma unroll
            for (int mt = 0; mt < 4; mt++)
                LDSM4(afr[mt], sA + sw_off(arow + mt * 16, ks * 2 + acsel));
#pragma unroll
            for (int nb = 0; nb < 2; nb++)
                LDSM4(bfr[nb], sB + sw_off(brow + nb * 16, ks * 2 + bcsel));
#pragma unroll
            for (int mt = 0; mt < 4; mt++) {
#pragma unroll
                for (int n8 = 0; n8 < 4; n8++) {
                    uint32_t bb[2] = { bfr[n8 >> 1][(n8 & 1) * 2], bfr[n8 >> 1][(n8 & 1) * 2 + 1] };
                    MMAS8(iacc[mt][n8], afr[mt], bb);
                }
            }
        }
    }

    // region 3 carries weight 1: value = fscale * (facc + iacc)
    if (!FUSE) {
#pragma unroll
        for (int mt = 0; mt < 4; mt++) {
            const int row = by * 128 + wm * 64 + mt * 16 + (lane >> 2);
#pragma unroll
            for (int n8 = 0; n8 < 4; n8++) {
                const int lc  = wn * 32 + n8 * 8 + (lane & 3) * 2;
                const int col = bx * 128 + lc;
                float2 v0, v1;
                v0.x = fscale * (facc[mt][n8][0] + (float)iacc[mt][n8][0]) + sBias[lc];
                v0.y = fscale * (facc[mt][n8][1] + (float)iacc[mt][n8][1]) + sBias[lc + 1];
                v1.x = fscale * (facc[mt][n8][2] + (float)iacc[mt][n8][2]) + sBias[lc];
                v1.y = fscale * (facc[mt][n8][3] + (float)iacc[mt][n8][3]) + sBias[lc + 1];
                *reinterpret_cast<float2*>(out + (size_t)row * Ntot + col)       = v0;
                *reinterpret_cast<float2*>(out + (size_t)(row + 8) * Ntot + col) = v1;
            }
        }
    } else {
#pragma unroll
        for (int mt = 0; mt < 4; mt++) {
            float pA = 0.f, pB = 0.f;
#pragma unroll
            for (int n8 = 0; n8 < 4; n8++) {
                const int lc = wn * 32 + n8 * 8 + (lane & 3) * 2;
                float h0 = fscale * (facc[mt][n8][0] + (float)iacc[mt][n8][0]) + sBias[lc];
                float h1 = fscale * (facc[mt][n8][1] + (float)iacc[mt][n8][1]) + sBias[lc + 1];
                float h2 = fscale * (facc[mt][n8][2] + (float)iacc[mt][n8][2]) + sBias[lc];
                float h3 = fscale * (facc[mt][n8][3] + (float)iacc[mt][n8][3]) + sBias[lc + 1];
                pA += gelu_exact(h0) * sW2[lc] + gelu_exact(h1) * sW2[lc + 1];
                pB += gelu_exact(h2) * sW2[lc] + gelu_exact(h3) * sW2[lc + 1];
            }
            pA += __shfl_xor_sync(0xffffffffu, pA, 1);
            pA += __shfl_xor_sync(0xffffffffu, pA, 2);
            pB += __shfl_xor_sync(0xffffffffu, pB, 1);
            pB += __shfl_xor_sync(0xffffffffu, pB, 2);
            if ((lane & 3) == 0) {
                atomicAdd(&sRow[wm * 64 + mt * 16 + (lane >> 2)],     pA);
                atomicAdd(&sRow[wm * 64 + mt * 16 + (lane >> 2) + 8], pB);
            }
        }
        __syncthreads();
        if (tid < 128)
            out[(size_t)(by * 128 + tid) * gridDim.x + bx] = sRow[tid];
    }
}

// ---------------- activation quant: f32 -> s8 hi + lo ----------------
__global__ __launch_bounds__(256)
void quant_act(const float4* __restrict__ X, char4* __restrict__ q1,
               char4* __restrict__ q0, float invr, int n4)
{
    int i = blockIdx.x * 256 + threadIdx.x;
    if (i >= n4) return;
    float4 x = X[i];
    int h0, h1, h2, h3, l0, l1, l2, l3;
    quant2(x.x, invr, h0, l0); quant2(x.y, invr, h1, l1);
    quant2(x.z, invr, h2, l2); quant2(x.w, invr, h3, l3);
    q1[i] = make_char4((char)h0, (char)h1, (char)h2, (char)h3);
    q0[i] = make_char4((char)l0, (char)l1, (char)l2, (char)l3);
}

// ---------------- weight transpose+quant: W[K,N] -> [N,4K]=[b1|b0|b1|b0] ----------------
__global__ __launch_bounds__(256)
void wquantT(const float* __restrict__ W, int8_t* __restrict__ dst, int K, int N)
{
    __shared__ float tile[32][33];
    const int k0 = blockIdx.x * 32, n0 = blockIdx.y * 32;
    const int tx = threadIdx.x & 31, ty8 = threadIdx.x >> 5;
#pragma unroll
    for (int i = 0; i < 4; i++) {
        int ty = ty8 + i * 8;
        tile[ty][tx] = W[(size_t)(k0 + ty) * N + n0 + tx];
    }
    __syncthreads();
#pragma unroll
    for (int i = 0; i < 4; i++) {
        int ny = ty8 + i * 8;
        int h, l;
        quant2(tile[tx][ny], INVR_W, h, l);
        int8_t* p = dst + (size_t)(n0 + ny) * 4 * K;
        p[k0 + tx]         = (int8_t)h;
        p[K + k0 + tx]     = (int8_t)l;
        p[2 * K + k0 + tx] = (int8_t)h;
        p[3 * K + k0 + tx] = (int8_t)l;
    }
}

// ---------------- block reduce ----------------
__device__ __forceinline__ float block_reduce_256(float val, float* sh) {
    int lane = threadIdx.x & 31, w = threadIdx.x >> 5;
#pragma unroll
    for (int o = 16; o > 0; o >>= 1) val += __shfl_down_sync(0xffffffffu, val, o);
    if (lane == 0) sh[w] = val;
    __syncthreads();
    if (w == 0) {
        float v2 = (lane < 8) ? sh[lane] : 0.f;
#pragma unroll
        for (int o = 4; o > 0; o >>= 1) v2 += __shfl_down_sync(0xffffffffu, v2, o);
        if (lane == 0) sh[0] = v2;
    }
    __syncthreads();
    float r = sh[0];
    __syncthreads();
    return r;
}

// ---------------- LayerNorm (in place, DM=256) ----------------
__global__ __launch_bounds__(256)
void ln_kernel(float* __restrict__ X)
{
    __shared__ float sh[8];
    const size_t row = blockIdx.x;
    float v = X[row * DMc + threadIdx.x];
    float mu = block_reduce_256(v, sh) * (1.f / DMc);
    float d = v - mu;
    float var = block_reduce_256(d * d, sh) * (1.f / DMc);
    X[row * DMc + threadIdx.x] = d * rsqrtf(var + 1e-5f);
}

// ---------------- fractional shift + causal 6-wide window average ----------------
__global__ __launch_bounds__(256)
void shiftctx_kernel(const float* __restrict__ theta)
{
    const int t = blockIdx.x, b = blockIdx.y, d = threadIdx.x;
    float th = fminf(fmaxf(theta[0], -12.f), 12.f);
    float delta = 2.f + 4.f / (1.f + expf(-th));
    float dl = fminf(fmaxf(delta, 0.f), (float)(Tc - 1));
    float nf = floorf(dl);
    float alpha = dl - nf;
    int ni = (int)nf;

    const int lo = max(0, t - 5);
    const float* arow = g_a + (size_t)b * Tc * DMc;
    float sum = 0.f;
    for (int tau = lo; tau <= t; tau++) {
        int i0 = min(max(tau - ni, 0), Tc - 1);
        int i1 = min(i0 + 1, Tc - 1);
        sum += (1.f - alpha) * arow[(size_t)i0 * DMc + d]
             +        alpha  * arow[(size_t)i1 * DMc + d];
    }
    g_actx[((size_t)b * Tc + t) * DMc + d] = sum / (float)(t - lo + 1);
}

// ---------------- build x features -> X1/X0 (int8, range 1) ----------------
__global__ __launch_bounds__(256)
void xbuild_kernel()
{
    __shared__ float sh[8];
    const size_t row = blockIdx.x;
    const int d = threadIdx.x;
    float vv = g_v[row * DMc + d];
    float aa = g_actx[row * DMc + d];
    float ssv = block_reduce_256(vv * vv, sh);
    float ssa = block_reduce_256(aa * aa, sh);
    float vn = vv / fmaxf(sqrtf(ssv), 1e-8f);
    float an = aa / fmaxf(sqrtf(ssa), 1e-8f);
    int h, l;
    size_t base = row * XDIM;
    quant2(an, INVR_X, h, l);
    g_X1[base + d] = (int8_t)h;           g_X0[base + d] = (int8_t)l;
    quant2(vn, INVR_X, h, l);
    g_X1[base + DMc + d] = (int8_t)h;     g_X0[base + DMc + d] = (int8_t)l;
    quant2(an * vn, INVR_X, h, l);
    g_X1[base + 2 * DMc + d] = (int8_t)h; g_X0[base + 2 * DMc + d] = (int8_t)l;
}

// ---------------- finalize ----------------
__global__ __launch_bounds__(256)
void final_kernel(const float* __restrict__ b2, float* __restrict__ out)
{
    const size_t row = blockIdx.x;
    const int d = threadIdx.x;
    float l = b2[0];
#pragma unroll
    for (int p = 0; p < 8; p++) l += g_part[row * 8 + p];
    l = fminf(fmaxf(l, -12.f), 12.f);
    float g = 1.f / (1.f + expf(-l));
    g = fminf(fmaxf(g, 0.05f), 0.95f);
    size_t idx = row * DMc + d;
    out[idx] = g * g_actx[idx] + (1.f - g) * g_v[idx];
}

// ---------------- launch ----------------
extern "C" void kernel_launch(void* const* d_in, const int* in_sizes, int n_in,
                              void* d_out, int out_size)
{
    const float* video = (const float*)d_in[0];
    const float* audio = (const float*)d_in[1];
    const float* Wv    = (const float*)d_in[2];
    const float* bv    = (const float*)d_in[3];
    const float* Wa    = (const float*)d_in[4];
    const float* ba    = (const float*)d_in[5];
    const float* theta = (const float*)d_in[6];
    const float* W1    = (const float*)d_in[7];
    const float* b1    = (const float*)d_in[8];
    const float* W2    = (const float*)d_in[9];
    const float* b2    = (const float*)d_in[10];
    float* out = (float*)d_out;

    float *gv, *ga, *gpart;
    int8_t *v1, *v0, *a1, *a0, *x1, *x0, *bvw, *baw, *b1w;
    cudaGetSymbolAddress((void**)&gv, g_v);
    cudaGetSymbolAddress((void**)&ga, g_a);
    cudaGetSymbolAddress((void**)&gpart, g_part);
    cudaGetSymbolAddress((void**)&v1, g_V1); cudaGetSymbolAddress((void**)&v0, g_V0);
    cudaGetSymbolAddress((void**)&a1, g_A1); cudaGetSymbolAddress((void**)&a0, g_A0);
    cudaGetSymbolAddress((void**)&x1, g_X1); cudaGetSymbolAddress((void**)&x0, g_X0);
    cudaGetSymbolAddress((void**)&bvw, g_Bv);
    cudaGetSymbolAddress((void**)&baw, g_Ba);
    cudaGetSymbolAddress((void**)&b1w, g_B1);

    cudaFuncSetAttribute(i8_gemm<false>, cudaFuncAttributeMaxDynamicSharedMemorySize, GSM_TOTAL);
    cudaFuncSetAttribute(i8_gemm<true>,  cudaFuncAttributeMaxDynamicSharedMemorySize, GSM_TOTAL);

    const float FS_PROJ = (8.f * 0.25f) / (QMAX * QMAX);   // act range 8, w range 0.25
    const float FS_X    = (1.f * 0.25f) / (QMAX * QMAX);   // act range 1, w range 0.25

    // quantize
    quant_act<<<(MROWS * VDIMc / 4 + 255) / 256, 256>>>(
        (const float4*)video, (char4*)v1, (char4*)v0, INVR_ACT, MROWS * VDIMc / 4);
    quant_act<<<(MROWS * ADIMc / 4 + 255) / 256, 256>>>(
        (const float4*)audio, (char4*)a1, (char4*)a0, INVR_ACT, MROWS * ADIMc / 4);
    wquantT<<<dim3(VDIMc / 32, DMc / 32), 256>>>(Wv, bvw, VDIMc, DMc);
    wquantT<<<dim3(ADIMc / 32, DMc / 32), 256>>>(Wa, baw, ADIMc, DMc);
    wquantT<<<dim3(XDIM / 32, HIDc / 32), 256>>>(W1, b1w, XDIM, HIDc);

    // projections
    i8_gemm<false><<<dim3(DMc / 128, MROWS / 128), 256, GSM_TOTAL>>>(
        v1, v0, bvw, bv, nullptr, gv, VDIMc, DMc, FS_PROJ);
    i8_gemm<false><<<dim3(DMc / 128, MROWS / 128), 256, GSM_TOTAL>>>(
        a1, a0, baw, ba, nullptr, ga, ADIMc, DMc, FS_PROJ);

    ln_kernel<<<MROWS, 256>>>(gv);
    ln_kernel<<<MROWS, 256>>>(ga);
    shiftctx_kernel<<<dim3(Tc, Bc), 256>>>(theta);
    xbuild_kernel<<<MROWS, 256>>>();

    // gate MLP with fused gelu + W2 reduction
    i8_gemm<true><<<dim3(HIDc / 128, MROWS / 128), 256, GSM_TOTAL>>>(
        x1, x0, b1w, b1, W2, gpart, XDIM, HIDc, FS_X);

    final_kernel<<<MROWS, 256>>>(b2, out);
}

// round 8
// speedup vs baseline: 2.4329x; 2.4329x over previous
#include <cuda_runtime.h>
#include <cuda_bf16.h>
#include <math.h>
#include <stdint.h>

// ---------------- problem constants ----------------
#define Bc     8
#define Tc     2048
#define VDIMc  1024
#define ADIMc  768
#define DMc    256
#define HIDc   1024
#define MROWS  (Bc * Tc)          // 16384
#define XDIM   (3 * DMc)          // 768

// ---------------- scratch (device globals; no allocation allowed) ----------------
__device__ float g_v   [MROWS * DMc];
__device__ float g_a   [MROWS * DMc];
__device__ float g_actx[MROWS * DMc];
__device__ float g_part[MROWS * 8];

__device__ __nv_bfloat16 g_Vhi[(size_t)MROWS * VDIMc];
__device__ __nv_bfloat16 g_Vlo[(size_t)MROWS * VDIMc];
__device__ __nv_bfloat16 g_Ahi[(size_t)MROWS * ADIMc];
__device__ __nv_bfloat16 g_Alo[(size_t)MROWS * ADIMc];
__device__ __nv_bfloat16 g_Xhi[(size_t)MROWS * XDIM];
__device__ __nv_bfloat16 g_Xlo[(size_t)MROWS * XDIM];
__device__ __nv_bfloat16 g_Bv[DMc  * 3 * VDIMc];   // [Bh|Bl|Bh] per row, [N,3K]
__device__ __nv_bfloat16 g_Ba[DMc  * 3 * ADIMc];
__device__ __nv_bfloat16 g_B1[HIDc * 3 * XDIM];

// ---------------- helpers ----------------
__device__ __forceinline__ uint32_t smem_u32(const void* p) {
    uint32_t a;
    asm("{ .reg .u64 t; cvta.to.shared.u64 t, %1; cvt.u32.u64 %0, t; }" : "=r"(a) : "l"(p));
    return a;
}
__device__ __forceinline__ void split1(float x, __nv_bfloat16& h, __nv_bfloat16& l) {
    h = __float2bfloat16(x);
    l = __float2bfloat16(x - __bfloat162float(h));
}
__device__ __forceinline__ float gelu_exact(float h) {
    return 0.5f * h * (1.f + erff(h * 0.70710678118654752f));
}

#define LDSM4(rg, addr) \
    asm volatile("ldmatrix.sync.aligned.m8n8.x4.shared.b16 {%0,%1,%2,%3}, [%4];" \
        : "=r"((rg)[0]), "=r"((rg)[1]), "=r"((rg)[2]), "=r"((rg)[3]) : "r"(addr))

#define MMA16816(d, a, b) \
    asm volatile("mma.sync.aligned.m16n8k16.row.col.f32.bf16.bf16.f32 " \
        "{%0,%1,%2,%3}, {%4,%5,%6,%7}, {%8,%9}, {%0,%1,%2,%3};" \
        : "+f"((d)[0]), "+f"((d)[1]), "+f"((d)[2]), "+f"((d)[3]) \
        : "r"((a)[0]), "r"((a)[1]), "r"((a)[2]), "r"((a)[3]), "r"((b)[0]), "r"((b)[1]))

#define CP_ASYNC16(dst, src) \
    asm volatile("cp.async.cg.shared.global [%0], [%1], 16;" :: "r"(dst), "l"(src) : "memory")
#define CP_COMMIT() asm volatile("cp.async.commit_group;" ::: "memory")
#define CP_WAIT1()  asm volatile("cp.async.wait_group 1;" ::: "memory")

// sub-tile: 128 rows x 64 bytes (32 bf16), XOR swizzle on 16B groups
__device__ __forceinline__ uint32_t sw_off(int r, int c16) {
    return (uint32_t)(((r << 6) + (c16 << 4)) ^ ((r & 3) << 4));
}

// ---------------- bf16 mma.sync GEMM ----------------
// C[M,Ntot] = [Ah|Ah|Al] @ [Bh|Bl|Bh]^T ; A hi/lo separate [M,K], B packed [Ntot,3K]
// stage = 2 k-chunks: {A0,A1,B0,B1} sub-tiles of 8KB each
#define STAGES 3
#define TILEB  32768
static constexpr int SM_EPI    = STAGES * TILEB;     // 98304
static constexpr int GSM_TOTAL = SM_EPI + 1536;      // 99840

template <bool FUSE>
__global__ void __launch_bounds__(256, 2)
mma_gemm(const __nv_bfloat16* __restrict__ Ahi, const __nv_bfloat16* __restrict__ Alo,
         const __nv_bfloat16* __restrict__ Bm,
         const float* __restrict__ bias, const float* __restrict__ W2,
         float* __restrict__ out, int K, int Ntot)
{
    extern __shared__ char smem[];
    const uint32_t sbase = smem_u32(smem);
    const int tid  = threadIdx.x;
    const int lane = tid & 31, warp = tid >> 5;
    const int wm = warp >> 2, wn = warp & 3;          // 2 x 4 warp grid (64m x 32n)
    const int bx = blockIdx.x, by = blockIdx.y;

    float* sBias = (float*)(smem + SM_EPI);
    float* sW2   = (float*)(smem + SM_EPI + 512);
    float* sRow  = (float*)(smem + SM_EPI + 1024);
    if (tid < 128) {
        sBias[tid] = bias[bx * 128 + tid];
        if (FUSE) { sW2[tid] = W2[bx * 128 + tid]; sRow[tid] = 0.f; }
    }

    const int ntK = K >> 5;           // 32-wide chunks per region
    const int nt  = 3 * ntK;          // total 32-chunks (even for all our K)
    const int ni  = nt >> 1;          // dual-chunk iterations
    const int K3  = 3 * K;

    const int cr = tid >> 2, cc = tid & 3;

    const __nv_bfloat16* Ah_b = Ahi + (size_t)(by * 128 + cr) * K + cc * 8;
    const __nv_bfloat16* Al_b = Alo + (size_t)(by * 128 + cr) * K + cc * 8;
    const __nv_bfloat16* Bb   = Bm  + (size_t)(bx * 128 + cr) * K3 + cc * 8;

    float acc[4][4][4];
#pragma unroll
    for (int i = 0; i < 4; i++)
#pragma unroll
        for (int j = 0; j < 4; j++)
#pragma unroll
            for (int q = 0; q < 4; q++) acc[i][j][q] = 0.f;

    auto load_pair = [&](int stage, int it) {
#pragma unroll
        for (int h = 0; h < 2; h++) {
            const int kt = 2 * it + h;
            int klocal = kt;
            const __nv_bfloat16* Ar;
            if (kt >= 2 * ntK)      { Ar = Al_b; klocal = kt - 2 * ntK; }
            else if (kt >= ntK)     { Ar = Ah_b; klocal = kt - ntK; }
            else                    { Ar = Ah_b; }
            const __nv_bfloat16* a0 = Ar + klocal * 32;
            const __nv_bfloat16* b0 = Bb + kt * 32;
            const uint32_t sA = sbase + stage * TILEB + h * 8192;
            const uint32_t sB = sbase + stage * TILEB + 16384 + h * 8192;
            CP_ASYNC16(sA + sw_off(cr,      cc), a0);
            CP_ASYNC16(sA + sw_off(cr + 64, cc), a0 + (size_t)64 * K);
            CP_ASYNC16(sB + sw_off(cr,      cc), b0);
            CP_ASYNC16(sB + sw_off(cr + 64, cc), b0 + (size_t)64 * K3);
        }
    };

    load_pair(0, 0); CP_COMMIT();
    load_pair(1, 1); CP_COMMIT();

    const int arow  = wm * 64 + (lane & 15);
    const int acsel = lane >> 4;
    const int brow  = wn * 32 + (lane & 7) + ((lane >> 4) << 3);
    const int bcsel = (lane >> 3) & 1;

    for (int it = 0; it < ni; it++) {
        CP_WAIT1();
        __syncthreads();

        const int nx = it + 2;
        if (nx < ni) load_pair(nx % STAGES, nx);
        CP_COMMIT();

#pragma unroll
        for (int h = 0; h < 2; h++) {
            const uint32_t sA = sbase + (it % STAGES) * TILEB + h * 8192;
            const uint32_t sB = sA + 16384;
#pragma unroll
            for (int ks = 0; ks < 2; ks++) {
                uint32_t afr[4][4], bfr[2][4];
#pragma unroll
                for (int mt = 0; mt < 4; mt++)
                    LDSM4(afr[mt], sA + sw_off(arow + mt * 16, ks * 2 + acsel));
#pragma unroll
                for (int nb = 0; nb < 2; nb++)
                    LDSM4(bfr[nb], sB + sw_off(brow + nb * 16, ks * 2 + bcsel));
#pragma unroll
                for (int mt = 0; mt < 4; mt++) {
#pragma unroll
                    for (int n8 = 0; n8 < 4; n8++) {
                        uint32_t bb[2] = { bfr[n8 >> 1][(n8 & 1) * 2], bfr[n8 >> 1][(n8 & 1) * 2 + 1] };
                        MMA16816(acc[mt][n8], afr[mt], bb);
                    }
                }
            }
        }
        // no trailing sync: next iteration's leading sync protects the stage
    }

    // ---- epilogue ----
    if (!FUSE) {
#pragma unroll
        for (int mt = 0; mt < 4; mt++) {
            const int row = by * 128 + wm * 64 + mt * 16 + (lane >> 2);
#pragma unroll
            for (int n8 = 0; n8 < 4; n8++) {
                const int lc  = wn * 32 + n8 * 8 + (lane & 3) * 2;
                const int col = bx * 128 + lc;
                float2 v0 = { acc[mt][n8][0] + sBias[lc], acc[mt][n8][1] + sBias[lc + 1] };
                float2 v1 = { acc[mt][n8][2] + sBias[lc], acc[mt][n8][3] + sBias[lc + 1] };
                *reinterpret_cast<float2*>(out + (size_t)row * Ntot + col)       = v0;
                *reinterpret_cast<float2*>(out + (size_t)(row + 8) * Ntot + col) = v1;
            }
        }
    } else {
#pragma unroll
        for (int mt = 0; mt < 4; mt++) {
            float pA = 0.f, pB = 0.f;
#pragma unroll
            for (int n8 = 0; n8 < 4; n8++) {
                const int lc = wn * 32 + n8 * 8 + (lane & 3) * 2;
                pA += gelu_exact(acc[mt][n8][0] + sBias[lc])     * sW2[lc];
                pA += gelu_exact(acc[mt][n8][1] + sBias[lc + 1]) * sW2[lc + 1];
                pB += gelu_exact(acc[mt][n8][2] + sBias[lc])     * sW2[lc];
                pB += gelu_exact(acc[mt][n8][3] + sBias[lc + 1]) * sW2[lc + 1];
            }
            pA += __shfl_xor_sync(0xffffffffu, pA, 1);
            pA += __shfl_xor_sync(0xffffffffu, pA, 2);
            pB += __shfl_xor_sync(0xffffffffu, pB, 1);
            pB += __shfl_xor_sync(0xffffffffu, pB, 2);
            if ((lane & 3) == 0) {
                atomicAdd(&sRow[wm * 64 + mt * 16 + (lane >> 2)],     pA);
                atomicAdd(&sRow[wm * 64 + mt * 16 + (lane >> 2) + 8], pB);
            }
        }
        __syncthreads();
        if (tid < 128)
            out[(size_t)(by * 128 + tid) * gridDim.x + bx] = sRow[tid];
    }
}

// ---------------- activation split: f32 -> bf16 hi + lo ----------------
__global__ __launch_bounds__(256)
void split_act(const float4* __restrict__ X, __nv_bfloat16* __restrict__ hi,
               __nv_bfloat16* __restrict__ lo, int n4)
{
    int i = blockIdx.x * 256 + threadIdx.x;
    if (i >= n4) return;
    float4 x = X[i];
    __nv_bfloat16 h0, h1, h2, h3, l0, l1, l2, l3;
    split1(x.x, h0, l0); split1(x.y, h1, l1); split1(x.z, h2, l2); split1(x.w, h3, l3);
    ushort4 hv = { __bfloat16_as_ushort(h0), __bfloat16_as_ushort(h1),
                   __bfloat16_as_ushort(h2), __bfloat16_as_ushort(h3) };
    ushort4 lv = { __bfloat16_as_ushort(l0), __bfloat16_as_ushort(l1),
                   __bfloat16_as_ushort(l2), __bfloat16_as_ushort(l3) };
    *reinterpret_cast<ushort4*>(hi + 4 * (size_t)i) = hv;
    *reinterpret_cast<ushort4*>(lo + 4 * (size_t)i) = lv;
}

// ---------------- tiled weight transpose+split: W[K,N] -> [N,3K]=[Bh|Bl|Bh] ----------------
__global__ __launch_bounds__(256)
void wsplit(const float* __restrict__ W, __nv_bfloat16* __restrict__ dst, int K, int N)
{
    __shared__ float tile[32][33];
    const int k0 = blockIdx.x * 32, n0 = blockIdx.y * 32;
    const int tx = threadIdx.x & 31, ty8 = threadIdx.x >> 5;
#pragma unroll
    for (int i = 0; i < 4; i++) {
        int ty = ty8 + i * 8;
        tile[ty][tx] = W[(size_t)(k0 + ty) * N + n0 + tx];
    }
    __syncthreads();
#pragma unroll
    for (int i = 0; i < 4; i++) {
        int ny = ty8 + i * 8;
        float x = tile[tx][ny];
        __nv_bfloat16 h, l;
        split1(x, h, l);
        __nv_bfloat16* p = dst + (size_t)(n0 + ny) * 3 * K;
        p[k0 + tx]         = h;
        p[K + k0 + tx]     = l;
        p[2 * K + k0 + tx] = h;
    }
}

// ---------------- warp-per-row LayerNorm (DM=256), 8 rows/block ----------------
__global__ __launch_bounds__(256)
void ln8_kernel(float* __restrict__ X)
{
    const int lane = threadIdx.x & 31, w = threadIdx.x >> 5;
    const size_t row = (size_t)blockIdx.x * 8 + w;
    float4* p = reinterpret_cast<float4*>(X + row * DMc);
    float4 x0 = p[lane], x1 = p[lane + 32];
    float s = x0.x + x0.y + x0.z + x0.w + x1.x + x1.y + x1.z + x1.w;
#pragma unroll
    for (int o = 16; o > 0; o >>= 1) s += __shfl_xor_sync(0xffffffffu, s, o);
    float mu = s * (1.f / DMc);
    x0.x -= mu; x0.y -= mu; x0.z -= mu; x0.w -= mu;
    x1.x -= mu; x1.y -= mu; x1.z -= mu; x1.w -= mu;
    float q = x0.x*x0.x + x0.y*x0.y + x0.z*x0.z + x0.w*x0.w
            + x1.x*x1.x + x1.y*x1.y + x1.z*x1.z + x1.w*x1.w;
#pragma unroll
    for (int o = 16; o > 0; o >>= 1) q += __shfl_xor_sync(0xffffffffu, q, o);
    float r = rsqrtf(q * (1.f / DMc) + 1e-5f);
    x0.x *= r; x0.y *= r; x0.z *= r; x0.w *= r;
    x1.x *= r; x1.y *= r; x1.z *= r; x1.w *= r;
    p[lane] = x0; p[lane + 32] = x1;
}

// ---------------- block reduce (256 threads) ----------------
__device__ __forceinline__ float block_reduce_256(float val, float* sh) {
    int lane = threadIdx.x & 31, w = threadIdx.x >> 5;
#pragma unroll
    for (int o = 16; o > 0; o >>= 1) val += __shfl_down_sync(0xffffffffu, val, o);
    if (lane == 0) sh[w] = val;
    __syncthreads();
    if (w == 0) {
        float v2 = (lane < 8) ? sh[lane] : 0.f;
#pragma unroll
        for (int o = 4; o > 0; o >>= 1) v2 += __shfl_down_sync(0xffffffffu, v2, o);
        if (lane == 0) sh[0] = v2;
    }
    __syncthreads();
    float r = sh[0];
    __syncthreads();
    return r;
}

// ---------------- fused: shift + window context + l2norm + X build ----------------
__global__ __launch_bounds__(256)
void shiftx_kernel(const float* __restrict__ theta)
{
    __shared__ float sh[8];
    const int t = blockIdx.x, b = blockIdx.y, d = threadIdx.x;
    float th = fminf(fmaxf(theta[0], -12.f), 12.f);
    float delta = 2.f + 4.f / (1.f + expf(-th));
    float dl = fminf(fmaxf(delta, 0.f), (float)(Tc - 1));
    float nf = floorf(dl);
    float alpha = dl - nf;
    int ni = (int)nf;

    const int lo = max(0, t - 5);
    const float* arow = g_a + (size_t)b * Tc * DMc;
    float sum = 0.f;
    for (int tau = lo; tau <= t; tau++) {
        int i0 = min(max(tau - ni, 0), Tc - 1);
        int i1 = min(i0 + 1, Tc - 1);
        sum += (1.f - alpha) * arow[(size_t)i0 * DMc + d]
             +        alpha  * arow[(size_t)i1 * DMc + d];
    }
    const size_t row = (size_t)b * Tc + t;
    float actx = sum / (float)(t - lo + 1);
    g_actx[row * DMc + d] = actx;

    float vv = g_v[row * DMc + d];
    float ssv = block_reduce_256(vv * vv, sh);
    float ssa = block_reduce_256(actx * actx, sh);
    float vn = vv   / fmaxf(sqrtf(ssv), 1e-8f);
    float an = actx / fmaxf(sqrtf(ssa), 1e-8f);
    __nv_bfloat16 h, l;
    size_t base = row * XDIM;
    split1(an,      h, l); g_Xhi[base + d]           = h; g_Xlo[base + d]           = l;
    split1(vn,      h, l); g_Xhi[base + DMc + d]     = h; g_Xlo[base + DMc + d]     = l;
    split1(an * vn, h, l); g_Xhi[base + 2 * DMc + d] = h; g_Xlo[base + 2 * DMc + d] = l;
}

// ---------------- finalize ----------------
__global__ __launch_bounds__(256)
void final_kernel(const float* __restrict__ b2, float* __restrict__ out)
{
    const size_t row = blockIdx.x;
    const int d = threadIdx.x;
    float l = b2[0];
#pragma unroll
    for (int p = 0; p < 8; p++) l += g_part[row * 8 + p];
    l = fminf(fmaxf(l, -12.f), 12.f);
    float g = 1.f / (1.f + expf(-l));
    g = fminf(fmaxf(g, 0.05f), 0.95f);
    size_t idx = row * DMc + d;
    out[idx] = g * g_actx[idx] + (1.f - g) * g_v[idx];
}

// ---------------- launch ----------------
extern "C" void kernel_launch(void* const* d_in, const int* in_sizes, int n_in,
                              void* d_out, int out_size)
{
    const float* video = (const float*)d_in[0];
    const float* audio = (const float*)d_in[1];
    const float* Wv    = (const float*)d_in[2];
    const float* bv    = (const float*)d_in[3];
    const float* Wa    = (const float*)d_in[4];
    const float* ba    = (const float*)d_in[5];
    const float* theta = (const float*)d_in[6];
    const float* W1    = (const float*)d_in[7];
    const float* b1    = (const float*)d_in[8];
    const float* W2    = (const float*)d_in[9];
    const float* b2    = (const float*)d_in[10];
    float* out = (float*)d_out;

    float *gv, *ga, *gpart;
    __nv_bfloat16 *vh, *vl, *ah, *al, *xh, *xl, *bvw, *baw, *b1w;
    cudaGetSymbolAddress((void**)&gv, g_v);
    cudaGetSymbolAddress((void**)&ga, g_a);
    cudaGetSymbolAddress((void**)&gpart, g_part);
    cudaGetSymbolAddress((void**)&vh, g_Vhi); cudaGetSymbolAddress((void**)&vl, g_Vlo);
    cudaGetSymbolAddress((void**)&ah, g_Ahi); cudaGetSymbolAddress((void**)&al, g_Alo);
    cudaGetSymbolAddress((void**)&xh, g_Xhi); cudaGetSymbolAddress((void**)&xl, g_Xlo);
    cudaGetSymbolAddress((void**)&bvw, g_Bv);
    cudaGetSymbolAddress((void**)&baw, g_Ba);
    cudaGetSymbolAddress((void**)&b1w, g_B1);

    cudaFuncSetAttribute(mma_gemm<false>, cudaFuncAttributeMaxDynamicSharedMemorySize, GSM_TOTAL);
    cudaFuncSetAttribute(mma_gemm<true>,  cudaFuncAttributeMaxDynamicSharedMemorySize, GSM_TOTAL);

    // splits
    split_act<<<(MROWS * (VDIMc / 4) + 255) / 256, 256>>>((const float4*)video, vh, vl, MROWS * VDIMc / 4);
    split_act<<<(MROWS * (ADIMc / 4) + 255) / 256, 256>>>((const float4*)audio, ah, al, MROWS * ADIMc / 4);
    wsplit<<<dim3(VDIMc / 32, DMc / 32), 256>>>(Wv, bvw, VDIMc, DMc);
    wsplit<<<dim3(ADIMc / 32, DMc / 32), 256>>>(Wa, baw, ADIMc, DMc);
    wsplit<<<dim3(XDIM / 32, HIDc / 32), 256>>>(W1, b1w, XDIM, HIDc);

    // projections
    mma_gemm<false><<<dim3(DMc / 128, MROWS / 128), 256, GSM_TOTAL>>>(
        vh, vl, bvw, bv, nullptr, gv, VDIMc, DMc);
    mma_gemm<false><<<dim3(DMc / 128, MROWS / 128), 256, GSM_TOTAL>>>(
        ah, al, baw, ba, nullptr, ga, ADIMc, DMc);

    // layernorms (warp-per-row)
    ln8_kernel<<<MROWS / 8, 256>>>(gv);
    ln8_kernel<<<MROWS / 8, 256>>>(ga);

    // fused shift + context + l2norm + X build
    shiftx_kernel<<<dim3(Tc, Bc), 256>>>(theta);

    // gate MLP with fused gelu + W2 reduction
    mma_gemm<true><<<dim3(HIDc / 128, MROWS / 128), 256, GSM_TOTAL>>>(
        xh, xl, b1w, b1, W2, gpart, XDIM, HIDc);

    final_kernel<<<MROWS, 256>>>(b2, out);
}

// round 9
// speedup vs baseline: 3.8434x; 1.5797x over previous
#include <cuda_runtime.h>
#include <cuda_fp16.h>
#include <math.h>
#include <stdint.h>

// ---------------- problem constants ----------------
#define Bc     8
#define Tc     2048
#define VDIMc  1024
#define ADIMc  768
#define DMc    256
#define HIDc   1024
#define MROWS  (Bc * Tc)          // 16384
#define XDIM   (3 * DMc)          // 768

// ---------------- scratch (device globals; no allocation allowed) ----------------
__device__ float g_v   [MROWS * DMc];
__device__ float g_a   [MROWS * DMc];
__device__ float g_actx[MROWS * DMc];
__device__ float g_part[MROWS * 8];

__device__ __half g_Vh[(size_t)MROWS * VDIMc];      // fp16 activations (1-term)
__device__ __half g_Ah[(size_t)MROWS * ADIMc];
__device__ __half g_Xh[(size_t)MROWS * XDIM];
__device__ __half g_Bv[DMc  * 2 * VDIMc];           // weights [N,2K] = [Bh|Bl]
__device__ __half g_Ba[DMc  * 2 * ADIMc];
__device__ __half g_B1[HIDc * 2 * XDIM];

// ---------------- helpers ----------------
__device__ __forceinline__ uint32_t smem_u32(const void* p) {
    uint32_t a;
    asm("{ .reg .u64 t; cvta.to.shared.u64 t, %1; cvt.u32.u64 %0, t; }" : "=r"(a) : "l"(p));
    return a;
}
__device__ __forceinline__ float gelu_exact(float h) {
    return 0.5f * h * (1.f + erff(h * 0.70710678118654752f));
}

#define LDSM4(rg, addr) \
    asm volatile("ldmatrix.sync.aligned.m8n8.x4.shared.b16 {%0,%1,%2,%3}, [%4];" \
        : "=r"((rg)[0]), "=r"((rg)[1]), "=r"((rg)[2]), "=r"((rg)[3]) : "r"(addr))

#define MMA16816(d, a, b) \
    asm volatile("mma.sync.aligned.m16n8k16.row.col.f32.f16.f16.f32 " \
        "{%0,%1,%2,%3}, {%4,%5,%6,%7}, {%8,%9}, {%0,%1,%2,%3};" \
        : "+f"((d)[0]), "+f"((d)[1]), "+f"((d)[2]), "+f"((d)[3]) \
        : "r"((a)[0]), "r"((a)[1]), "r"((a)[2]), "r"((a)[3]), "r"((b)[0]), "r"((b)[1]))

#define CP_ASYNC16(dst, src) \
    asm volatile("cp.async.cg.shared.global [%0], [%1], 16;" :: "r"(dst), "l"(src) : "memory")
#define CP_COMMIT() asm volatile("cp.async.commit_group;" ::: "memory")
#define CP_WAIT1()  asm volatile("cp.async.wait_group 1;" ::: "memory")

// sub-tile: 128 rows x 64 bytes (32 fp16), XOR swizzle on 16B groups
__device__ __forceinline__ uint32_t sw_off(int r, int c16) {
    return (uint32_t)(((r << 6) + (c16 << 4)) ^ ((r & 3) << 4));
}

// ---------------- fp16 asymmetric-split GEMM ----------------
// C[M,Ntot] = A_f16 @ (Bh + Bl)^T ; A [M,K] fp16, B packed [Ntot,2K] = [Bh|Bl]
// stage = {A, Bh, Bl} sub-tiles of 8KB each; A fragments reused for both B regions
#define STAGES 3
#define STAGEB 24576
static constexpr int SM_EPI    = STAGES * STAGEB;    // 73728
static constexpr int GSM_TOTAL = SM_EPI + 1536;      // 75264

template <bool FUSE>
__global__ void __launch_bounds__(256, 2)
mma_gemm(const __half* __restrict__ A, const __half* __restrict__ Bm,
         const float* __restrict__ bias, const float* __restrict__ W2,
         float* __restrict__ out, int K, int Ntot)
{
    extern __shared__ char smem[];
    const uint32_t sbase = smem_u32(smem);
    const int tid  = threadIdx.x;
    const int lane = tid & 31, warp = tid >> 5;
    const int wm = warp >> 2, wn = warp & 3;          // 2 x 4 warp grid (64m x 32n)
    const int bx = blockIdx.x, by = blockIdx.y;

    float* sBias = (float*)(smem + SM_EPI);
    float* sW2   = (float*)(smem + SM_EPI + 512);
    float* sRow  = (float*)(smem + SM_EPI + 1024);
    if (tid < 128) {
        sBias[tid] = bias[bx * 128 + tid];
        if (FUSE) { sW2[tid] = W2[bx * 128 + tid]; sRow[tid] = 0.f; }
    }

    const int ntK = K >> 5;           // 32-wide k-chunks
    const int K2  = 2 * K;

    const int cr = tid >> 2, cc = tid & 3;

    const __half* Ab = A  + (size_t)(by * 128 + cr) * K  + cc * 8;
    const __half* Bb = Bm + (size_t)(bx * 128 + cr) * K2 + cc * 8;

    float acc[4][4][4];
#pragma unroll
    for (int i = 0; i < 4; i++)
#pragma unroll
        for (int j = 0; j < 4; j++)
#pragma unroll
            for (int q = 0; q < 4; q++) acc[i][j][q] = 0.f;

    auto load_stage = [&](int stage, int kt) {
        const uint32_t sA  = sbase + stage * STAGEB;
        const __half* a0  = Ab + kt * 32;
        const __half* bh0 = Bb + kt * 32;
        const __half* bl0 = Bb + K + kt * 32;
        CP_ASYNC16(sA         + sw_off(cr,      cc), a0);
        CP_ASYNC16(sA         + sw_off(cr + 64, cc), a0  + (size_t)64 * K);
        CP_ASYNC16(sA + 8192  + sw_off(cr,      cc), bh0);
        CP_ASYNC16(sA + 8192  + sw_off(cr + 64, cc), bh0 + (size_t)64 * K2);
        CP_ASYNC16(sA + 16384 + sw_off(cr,      cc), bl0);
        CP_ASYNC16(sA + 16384 + sw_off(cr + 64, cc), bl0 + (size_t)64 * K2);
    };

    load_stage(0, 0); CP_COMMIT();
    load_stage(1, 1); CP_COMMIT();

    const int arow  = wm * 64 + (lane & 15);
    const int acsel = lane >> 4;
    const int brow  = wn * 32 + (lane & 7) + ((lane >> 4) << 3);
    const int bcsel = (lane >> 3) & 1;

    for (int kt = 0; kt < ntK; kt++) {
        CP_WAIT1();
        __syncthreads();

        const int nx = kt + 2;
        if (nx < ntK) load_stage(nx % STAGES, nx);
        CP_COMMIT();

        const uint32_t sA  = sbase + (kt % STAGES) * STAGEB;
        const uint32_t sBh = sA + 8192;
        const uint32_t sBl = sA + 16384;
#pragma unroll
        for (int ks = 0; ks < 2; ks++) {
            uint32_t afr[4][4], bh[2][4], bl[2][4];
#pragma unroll
            for (int mt = 0; mt < 4; mt++)
                LDSM4(afr[mt], sA + sw_off(arow + mt * 16, ks * 2 + acsel));
#pragma unroll
            for (int nb = 0; nb < 2; nb++) {
                LDSM4(bh[nb], sBh + sw_off(brow + nb * 16, ks * 2 + bcsel));
                LDSM4(bl[nb], sBl + sw_off(brow + nb * 16, ks * 2 + bcsel));
            }
#pragma unroll
            for (int mt = 0; mt < 4; mt++) {
#pragma unroll
                for (int n8 = 0; n8 < 4; n8++) {
                    uint32_t bbh[2] = { bh[n8 >> 1][(n8 & 1) * 2], bh[n8 >> 1][(n8 & 1) * 2 + 1] };
                    MMA16816(acc[mt][n8], afr[mt], bbh);
                    uint32_t bbl[2] = { bl[n8 >> 1][(n8 & 1) * 2], bl[n8 >> 1][(n8 & 1) * 2 + 1] };
                    MMA16816(acc[mt][n8], afr[mt], bbl);
                }
            }
        }
        // no trailing sync: next iteration's leading sync protects the stage
    }

    // ---- epilogue ----
    if (!FUSE) {
#pragma unroll
        for (int mt = 0; mt < 4; mt++) {
            const int row = by * 128 + wm * 64 + mt * 16 + (lane >> 2);
#pragma unroll
            for (int n8 = 0; n8 < 4; n8++) {
                const int lc  = wn * 32 + n8 * 8 + (lane & 3) * 2;
                const int col = bx * 128 + lc;
                float2 v0 = { acc[mt][n8][0] + sBias[lc], acc[mt][n8][1] + sBias[lc + 1] };
                float2 v1 = { acc[mt][n8][2] + sBias[lc], acc[mt][n8][3] + sBias[lc + 1] };
                *reinterpret_cast<float2*>(out + (size_t)row * Ntot + col)       = v0;
                *reinterpret_cast<float2*>(out + (size_t)(row + 8) * Ntot + col) = v1;
            }
        }
    } else {
#pragma unroll
        for (int mt = 0; mt < 4; mt++) {
            float pA = 0.f, pB = 0.f;
#pragma unroll
            for (int n8 = 0; n8 < 4; n8++) {
                const int lc = wn * 32 + n8 * 8 + (lane & 3) * 2;
                pA += gelu_exact(acc[mt][n8][0] + sBias[lc])     * sW2[lc];
                pA += gelu_exact(acc[mt][n8][1] + sBias[lc + 1]) * sW2[lc + 1];
                pB += gelu_exact(acc[mt][n8][2] + sBias[lc])     * sW2[lc];
                pB += gelu_exact(acc[mt][n8][3] + sBias[lc + 1]) * sW2[lc + 1];
            }
            pA += __shfl_xor_sync(0xffffffffu, pA, 1);
            pA += __shfl_xor_sync(0xffffffffu, pA, 2);
            pB += __shfl_xor_sync(0xffffffffu, pB, 1);
            pB += __shfl_xor_sync(0xffffffffu, pB, 2);
            if ((lane & 3) == 0) {
                atomicAdd(&sRow[wm * 64 + mt * 16 + (lane >> 2)],     pA);
                atomicAdd(&sRow[wm * 64 + mt * 16 + (lane >> 2) + 8], pB);
            }
        }
        __syncthreads();
        if (tid < 128)
            out[(size_t)(by * 128 + tid) * gridDim.x + bx] = sRow[tid];
    }
}

// ---------------- activation convert: f32 -> fp16 (single term) ----------------
__global__ __launch_bounds__(256)
void cvt_act(const float4* __restrict__ X, __half* __restrict__ dst, int n4)
{
    int i = blockIdx.x * 256 + threadIdx.x;
    if (i >= n4) return;
    float4 x = X[i];
    ushort4 v;
    v.x = __half_as_ushort(__float2half(x.x));
    v.y = __half_as_ushort(__float2half(x.y));
    v.z = __half_as_ushort(__float2half(x.z));
    v.w = __half_as_ushort(__float2half(x.w));
    *reinterpret_cast<ushort4*>(dst + 4 * (size_t)i) = v;
}

// ---------------- tiled weight transpose+split: W[K,N] -> [N,2K]=[Bh|Bl] fp16 ----------------
__global__ __launch_bounds__(256)
void wsplit(const float* __restrict__ W, __half* __restrict__ dst, int K, int N)
{
    __shared__ float tile[32][33];
    const int k0 = blockIdx.x * 32, n0 = blockIdx.y * 32;
    const int tx = threadIdx.x & 31, ty8 = threadIdx.x >> 5;
#pragma unroll
    for (int i = 0; i < 4; i++) {
        int ty = ty8 + i * 8;
        tile[ty][tx] = W[(size_t)(k0 + ty) * N + n0 + tx];
    }
    __syncthreads();
#pragma unroll
    for (int i = 0; i < 4; i++) {
        int ny = ty8 + i * 8;
        float x = tile[tx][ny];
        __half h = __float2half(x);
        __half l = __float2half(x - __half2float(h));
        __half* p = dst + (size_t)(n0 + ny) * 2 * K;
        p[k0 + tx]     = h;
        p[K + k0 + tx] = l;
    }
}

// ---------------- warp-per-row LayerNorm (DM=256), 8 rows/block ----------------
__global__ __launch_bounds__(256)
void ln8_kernel(float* __restrict__ X)
{
    const int lane = threadIdx.x & 31, w = threadIdx.x >> 5;
    const size_t row = (size_t)blockIdx.x * 8 + w;
    float4* p = reinterpret_cast<float4*>(X + row * DMc);
    float4 x0 = p[lane], x1 = p[lane + 32];
    float s = x0.x + x0.y + x0.z + x0.w + x1.x + x1.y + x1.z + x1.w;
#pragma unroll
    for (int o = 16; o > 0; o >>= 1) s += __shfl_xor_sync(0xffffffffu, s, o);
    float mu = s * (1.f / DMc);
    x0.x -= mu; x0.y -= mu; x0.z -= mu; x0.w -= mu;
    x1.x -= mu; x1.y -= mu; x1.z -= mu; x1.w -= mu;
    float q = x0.x*x0.x + x0.y*x0.y + x0.z*x0.z + x0.w*x0.w
            + x1.x*x1.x + x1.y*x1.y + x1.z*x1.z + x1.w*x1.w;
#pragma unroll
    for (int o = 16; o > 0; o >>= 1) q += __shfl_xor_sync(0xffffffffu, q, o);
    float r = rsqrtf(q * (1.f / DMc) + 1e-5f);
    x0.x *= r; x0.y *= r; x0.z *= r; x0.w *= r;
    x1.x *= r; x1.y *= r; x1.z *= r; x1.w *= r;
    p[lane] = x0; p[lane + 32] = x1;
}

// ---------------- block reduce (256 threads) ----------------
__device__ __forceinline__ float block_reduce_256(float val, float* sh) {
    int lane = threadIdx.x & 31, w = threadIdx.x >> 5;
#pragma unroll
    for (int o = 16; o > 0; o >>= 1) val += __shfl_down_sync(0xffffffffu, val, o);
    if (lane == 0) sh[w] = val;
    __syncthreads();
    if (w == 0) {
        float v2 = (lane < 8) ? sh[lane] : 0.f;
#pragma unroll
        for (int o = 4; o > 0; o >>= 1) v2 += __shfl_down_sync(0xffffffffu, v2, o);
        if (lane == 0) sh[0] = v2;
    }
    __syncthreads();
    float r = sh[0];
    __syncthreads();
    return r;
}

// ---------------- fused: shift + window context + l2norm + X build (fp16) ----------------
__global__ __launch_bounds__(256)
void shiftx_kernel(const float* __restrict__ theta)
{
    __shared__ float sh[8];
    const int t = blockIdx.x, b = blockIdx.y, d = threadIdx.x;
    float th = fminf(fmaxf(theta[0], -12.f), 12.f);
    float delta = 2.f + 4.f / (1.f + expf(-th));
    float dl = fminf(fmaxf(delta, 0.f), (float)(Tc - 1));
    float nf = floorf(dl);
    float alpha = dl - nf;
    int ni = (int)nf;

    const int lo = max(0, t - 5);
    const float* arow = g_a + (size_t)b * Tc * DMc;
    float sum = 0.f;
    for (int tau = lo; tau <= t; tau++) {
        int i0 = min(max(tau - ni, 0), Tc - 1);
        int i1 = min(i0 + 1, Tc - 1);
        sum += (1.f - alpha) * arow[(size_t)i0 * DMc + d]
             +        alpha  * arow[(size_t)i1 * DMc + d];
    }
    const size_t row = (size_t)b * Tc + t;
    float actx = sum / (float)(t - lo + 1);
    g_actx[row * DMc + d] = actx;

    float vv = g_v[row * DMc + d];
    float ssv = block_reduce_256(vv * vv, sh);
    float ssa = block_reduce_256(actx * actx, sh);
    float vn = vv   / fmaxf(sqrtf(ssv), 1e-8f);
    float an = actx / fmaxf(sqrtf(ssa), 1e-8f);
    size_t base = row * XDIM;
    g_Xh[base + d]           = __float2half(an);
    g_Xh[base + DMc + d]     = __float2half(vn);
    g_Xh[base + 2 * DMc + d] = __float2half(an * vn);
}

// ---------------- finalize ----------------
__global__ __launch_bounds__(256)
void final_kernel(const float* __restrict__ b2, float* __restrict__ out)
{
    const size_t row = blockIdx.x;
    const int d = threadIdx.x;
    float l = b2[0];
#pragma unroll
    for (int p = 0; p < 8; p++) l += g_part[row * 8 + p];
    l = fminf(fmaxf(l, -12.f), 12.f);
    float g = 1.f / (1.f + expf(-l));
    g = fminf(fmaxf(g, 0.05f), 0.95f);
    size_t idx = row * DMc + d;
    out[idx] = g * g_actx[idx] + (1.f - g) * g_v[idx];
}

// ---------------- launch ----------------
extern "C" void kernel_launch(void* const* d_in, const int* in_sizes, int n_in,
                              void* d_out, int out_size)
{
    const float* video = (const float*)d_in[0];
    const float* audio = (const float*)d_in[1];
    const float* Wv    = (const float*)d_in[2];
    const float* bv    = (const float*)d_in[3];
    const float* Wa    = (const float*)d_in[4];
    const float* ba    = (const float*)d_in[5];
    const float* theta = (const float*)d_in[6];
    const float* W1    = (const float*)d_in[7];
    const float* b1    = (const float*)d_in[8];
    const float* W2    = (const float*)d_in[9];
    const float* b2    = (const float*)d_in[10];
    float* out = (float*)d_out;

    float *gv, *ga, *gpart;
    __half *vh, *ah, *xh, *bvw, *baw, *b1w;
    cudaGetSymbolAddress((void**)&gv, g_v);
    cudaGetSymbolAddress((void**)&ga, g_a);
    cudaGetSymbolAddress((void**)&gpart, g_part);
    cudaGetSymbolAddress((void**)&vh, g_Vh);
    cudaGetSymbolAddress((void**)&ah, g_Ah);
    cudaGetSymbolAddress((void**)&xh, g_Xh);
    cudaGetSymbolAddress((void**)&bvw, g_Bv);
    cudaGetSymbolAddress((void**)&baw, g_Ba);
    cudaGetSymbolAddress((void**)&b1w, g_B1);

    cudaFuncSetAttribute(mma_gemm<false>, cudaFuncAttributeMaxDynamicSharedMemorySize, GSM_TOTAL);
    cudaFuncSetAttribute(mma_gemm<true>,  cudaFuncAttributeMaxDynamicSharedMemorySize, GSM_TOTAL);

    // converts / splits
    cvt_act<<<(MROWS * (VDIMc / 4) + 255) / 256, 256>>>((const float4*)video, vh, MROWS * VDIMc / 4);
    cvt_act<<<(MROWS * (ADIMc / 4) + 255) / 256, 256>>>((const float4*)audio, ah, MROWS * ADIMc / 4);
    wsplit<<<dim3(VDIMc / 32, DMc / 32), 256>>>(Wv, bvw, VDIMc, DMc);
    wsplit<<<dim3(ADIMc / 32, DMc / 32), 256>>>(Wa, baw, ADIMc, DMc);
    wsplit<<<dim3(XDIM / 32, HIDc / 32), 256>>>(W1, b1w, XDIM, HIDc);

    // projections
    mma_gemm<false><<<dim3(DMc / 128, MROWS / 128), 256, GSM_TOTAL>>>(
        vh, bvw, bv, nullptr, gv, VDIMc, DMc);
    mma_gemm<false><<<dim3(DMc / 128, MROWS / 128), 256, GSM_TOTAL>>>(
        ah, baw, ba, nullptr, ga, ADIMc, DMc);

    // layernorms (warp-per-row)
    ln8_kernel<<<MROWS / 8, 256>>>(gv);
    ln8_kernel<<<MROWS / 8, 256>>>(ga);

    // fused shift + context + l2norm + X build
    shiftx_kernel<<<dim3(Tc, Bc), 256>>>(theta);

    // gate MLP with fused gelu + W2 reduction
    mma_gemm<true><<<dim3(HIDc / 128, MROWS / 128), 256, GSM_TOTAL>>>(
        xh, b1w, b1, W2, gpart, XDIM, HIDc);

    final_kernel<<<MROWS, 256>>>(b2, out);
}

// round 10
// speedup vs baseline: 5.0621x; 1.3171x over previous
#include <cuda_runtime.h>
#include <cuda_fp16.h>
#include <math.h>
#include <stdint.h>

// ---------------- problem constants ----------------
#define Bc     8
#define Tc     2048
#define VDIMc  1024
#define ADIMc  768
#define DMc    256
#define HIDc   1024
#define MROWS  (Bc * Tc)          // 16384
#define XDIM   (3 * DMc)          // 768

// ---------------- scratch (device globals; no allocation allowed) ----------------
__device__ float g_v   [MROWS * DMc];
__device__ float g_a   [MROWS * DMc];
__device__ float g_actx[MROWS * DMc];
__device__ float g_part[MROWS * 8];

__device__ __half g_Vh[(size_t)MROWS * VDIMc];      // fp16 activations
__device__ __half g_Ah[(size_t)MROWS * ADIMc];
__device__ __half g_Xh[(size_t)MROWS * XDIM];
__device__ __half g_Bv[DMc  * VDIMc];               // fp16 transposed weights [N,K]
__device__ __half g_Ba[DMc  * ADIMc];
__device__ __half g_B1[HIDc * XDIM];

// ---------------- helpers ----------------
__device__ __forceinline__ uint32_t smem_u32(const void* p) {
    uint32_t a;
    asm("{ .reg .u64 t; cvta.to.shared.u64 t, %1; cvt.u32.u64 %0, t; }" : "=r"(a) : "l"(p));
    return a;
}
__device__ __forceinline__ float gelu_exact(float h) {
    return 0.5f * h * (1.f + erff(h * 0.70710678118654752f));
}

#define LDSM4(rg, addr) \
    asm volatile("ldmatrix.sync.aligned.m8n8.x4.shared.b16 {%0,%1,%2,%3}, [%4];" \
        : "=r"((rg)[0]), "=r"((rg)[1]), "=r"((rg)[2]), "=r"((rg)[3]) : "r"(addr))

#define MMA16816(d, a, b) \
    asm volatile("mma.sync.aligned.m16n8k16.row.col.f32.f16.f16.f32 " \
        "{%0,%1,%2,%3}, {%4,%5,%6,%7}, {%8,%9}, {%0,%1,%2,%3};" \
        : "+f"((d)[0]), "+f"((d)[1]), "+f"((d)[2]), "+f"((d)[3]) \
        : "r"((a)[0]), "r"((a)[1]), "r"((a)[2]), "r"((a)[3]), "r"((b)[0]), "r"((b)[1]))

#define CP_ASYNC16(dst, src) \
    asm volatile("cp.async.cg.shared.global [%0], [%1], 16;" :: "r"(dst), "l"(src) : "memory")
#define CP_COMMIT() asm volatile("cp.async.commit_group;" ::: "memory")
#define CP_WAIT1()  asm volatile("cp.async.wait_group 1;" ::: "memory")

// sub-tile: 128 rows x 64 bytes (32 fp16), XOR swizzle on 16B groups
__device__ __forceinline__ uint32_t sw_off(int r, int c16) {
    return (uint32_t)(((r << 6) + (c16 << 4)) ^ ((r & 3) << 4));
}

// ---------------- plain fp16 GEMM: C[M,Ntot] = A @ B^T (+bias) ----------------
// stage = 2 k-chunks {A0,B0,A1,B1}, 8KB sub-tiles -> 32KB/stage
#define STAGES 3
#define STAGEB 32768
static constexpr int SM_EPI    = STAGES * STAGEB;    // 98304
static constexpr int GSM_TOTAL = SM_EPI + 1536;      // 99840

template <bool FUSE>
__global__ void __launch_bounds__(256, 2)
mma_gemm(const __half* __restrict__ A, const __half* __restrict__ Bm,
         const float* __restrict__ bias, const float* __restrict__ W2,
         float* __restrict__ out, int K, int Ntot)
{
    extern __shared__ char smem[];
    const uint32_t sbase = smem_u32(smem);
    const int tid  = threadIdx.x;
    const int lane = tid & 31, warp = tid >> 5;
    const int wm = warp >> 2, wn = warp & 3;          // 2 x 4 warp grid (64m x 32n)
    const int bx = blockIdx.x, by = blockIdx.y;

    float* sBias = (float*)(smem + SM_EPI);
    float* sW2   = (float*)(smem + SM_EPI + 512);
    float* sRow  = (float*)(smem + SM_EPI + 1024);
    if (tid < 128) {
        sBias[tid] = bias[bx * 128 + tid];
        if (FUSE) { sW2[tid] = W2[bx * 128 + tid]; sRow[tid] = 0.f; }
    }

    const int ni = K >> 6;            // dual-chunk iterations (64 K each)

    const int cr = tid >> 2, cc = tid & 3;

    const __half* Ab = A  + (size_t)(by * 128 + cr) * K + cc * 8;
    const __half* Bb = Bm + (size_t)(bx * 128 + cr) * K + cc * 8;

    float acc[4][4][4];
#pragma unroll
    for (int i = 0; i < 4; i++)
#pragma unroll
        for (int j = 0; j < 4; j++)
#pragma unroll
            for (int q = 0; q < 4; q++) acc[i][j][q] = 0.f;

    auto load_stage = [&](int stage, int it) {
        const uint32_t s0 = sbase + stage * STAGEB;
#pragma unroll
        for (int h = 0; h < 2; h++) {
            const int kofs = (2 * it + h) * 32;
            const __half* a0 = Ab + kofs;
            const __half* b0 = Bb + kofs;
            const uint32_t sA = s0 + h * 16384;
            const uint32_t sB = sA + 8192;
            CP_ASYNC16(sA + sw_off(cr,      cc), a0);
            CP_ASYNC16(sA + sw_off(cr + 64, cc), a0 + (size_t)64 * K);
            CP_ASYNC16(sB + sw_off(cr,      cc), b0);
            CP_ASYNC16(sB + sw_off(cr + 64, cc), b0 + (size_t)64 * K);
        }
    };

    load_stage(0, 0); CP_COMMIT();
    load_stage(1, 1); CP_COMMIT();

    const int arow  = wm * 64 + (lane & 15);
    const int acsel = lane >> 4;
    const int brow  = wn * 32 + (lane & 7) + ((lane >> 4) << 3);
    const int bcsel = (lane >> 3) & 1;

    for (int it = 0; it < ni; it++) {
        CP_WAIT1();
        __syncthreads();

        const int nx = it + 2;
        if (nx < ni) load_stage(nx % STAGES, nx);
        CP_COMMIT();

#pragma unroll
        for (int h = 0; h < 2; h++) {
            const uint32_t sA = sbase + (it % STAGES) * STAGEB + h * 16384;
            const uint32_t sB = sA + 8192;
#pragma unroll
            for (int ks = 0; ks < 2; ks++) {
                uint32_t afr[4][4], bfr[2][4];
#pragma unroll
                for (int mt = 0; mt < 4; mt++)
                    LDSM4(afr[mt], sA + sw_off(arow + mt * 16, ks * 2 + acsel));
#pragma unroll
                for (int nb = 0; nb < 2; nb++)
                    LDSM4(bfr[nb], sB + sw_off(brow + nb * 16, ks * 2 + bcsel));
#pragma unroll
                for (int mt = 0; mt < 4; mt++) {
#pragma unroll
                    for (int n8 = 0; n8 < 4; n8++) {
                        uint32_t bb[2] = { bfr[n8 >> 1][(n8 & 1) * 2], bfr[n8 >> 1][(n8 & 1) * 2 + 1] };
                        MMA16816(acc[mt][n8], afr[mt], bb);
                    }
                }
            }
        }
        // no trailing sync: next iteration's leading sync protects the stage
    }

    // ---- epilogue ----
    if (!FUSE) {
#pragma unroll
        for (int mt = 0; mt < 4; mt++) {
            const int row = by * 128 + wm * 64 + mt * 16 + (lane >> 2);
#pragma unroll
            for (int n8 = 0; n8 < 4; n8++) {
                const int lc  = wn * 32 + n8 * 8 + (lane & 3) * 2;
                const int col = bx * 128 + lc;
                float2 v0 = { acc[mt][n8][0] + sBias[lc], acc[mt][n8][1] + sBias[lc + 1] };
                float2 v1 = { acc[mt][n8][2] + sBias[lc], acc[mt][n8][3] + sBias[lc + 1] };
                *reinterpret_cast<float2*>(out + (size_t)row * Ntot + col)       = v0;
                *reinterpret_cast<float2*>(out + (size_t)(row + 8) * Ntot + col) = v1;
            }
        }
    } else {
#pragma unroll
        for (int mt = 0; mt < 4; mt++) {
            float pA = 0.f, pB = 0.f;
#pragma unroll
            for (int n8 = 0; n8 < 4; n8++) {
                const int lc = wn * 32 + n8 * 8 + (lane & 3) * 2;
                pA += gelu_exact(acc[mt][n8][0] + sBias[lc])     * sW2[lc];
                pA += gelu_exact(acc[mt][n8][1] + sBias[lc + 1]) * sW2[lc + 1];
                pB += gelu_exact(acc[mt][n8][2] + sBias[lc])     * sW2[lc];
                pB += gelu_exact(acc[mt][n8][3] + sBias[lc + 1]) * sW2[lc + 1];
            }
            pA += __shfl_xor_sync(0xffffffffu, pA, 1);
            pA += __shfl_xor_sync(0xffffffffu, pA, 2);
            pB += __shfl_xor_sync(0xffffffffu, pB, 1);
            pB += __shfl_xor_sync(0xffffffffu, pB, 2);
            if ((lane & 3) == 0) {
                atomicAdd(&sRow[wm * 64 + mt * 16 + (lane >> 2)],     pA);
                atomicAdd(&sRow[wm * 64 + mt * 16 + (lane >> 2) + 8], pB);
            }
        }
        __syncthreads();
        if (tid < 128)
            out[(size_t)(by * 128 + tid) * gridDim.x + bx] = sRow[tid];
    }
}

// ---------------- activation convert: f32 -> fp16 ----------------
__global__ __launch_bounds__(256)
void cvt_act(const float4* __restrict__ X, __half* __restrict__ dst, int n4)
{
    int i = blockIdx.x * 256 + threadIdx.x;
    if (i >= n4) return;
    float4 x = X[i];
    ushort4 v;
    v.x = __half_as_ushort(__float2half(x.x));
    v.y = __half_as_ushort(__float2half(x.y));
    v.z = __half_as_ushort(__float2half(x.z));
    v.w = __half_as_ushort(__float2half(x.w));
    *reinterpret_cast<ushort4*>(dst + 4 * (size_t)i) = v;
}

// ---------------- tiled weight convert+transpose: W[K,N] -> [N,K] fp16 ----------------
__global__ __launch_bounds__(256)
void wcvtT(const float* __restrict__ W, __half* __restrict__ dst, int K, int N)
{
    __shared__ float tile[32][33];
    const int k0 = blockIdx.x * 32, n0 = blockIdx.y * 32;
    const int tx = threadIdx.x & 31, ty8 = threadIdx.x >> 5;
#pragma unroll
    for (int i = 0; i < 4; i++) {
        int ty = ty8 + i * 8;
        tile[ty][tx] = W[(size_t)(k0 + ty) * N + n0 + tx];
    }
    __syncthreads();
#pragma unroll
    for (int i = 0; i < 4; i++) {
        int ny = ty8 + i * 8;
        dst[(size_t)(n0 + ny) * K + k0 + tx] = __float2half(tile[tx][ny]);
    }
}

// ---------------- warp-per-row LayerNorm (DM=256), 8 rows/block ----------------
__global__ __launch_bounds__(256)
void ln8_kernel(float* __restrict__ X)
{
    const int lane = threadIdx.x & 31, w = threadIdx.x >> 5;
    const size_t row = (size_t)blockIdx.x * 8 + w;
    float4* p = reinterpret_cast<float4*>(X + row * DMc);
    float4 x0 = p[lane], x1 = p[lane + 32];
    float s = x0.x + x0.y + x0.z + x0.w + x1.x + x1.y + x1.z + x1.w;
#pragma unroll
    for (int o = 16; o > 0; o >>= 1) s += __shfl_xor_sync(0xffffffffu, s, o);
    float mu = s * (1.f / DMc);
    x0.x -= mu; x0.y -= mu; x0.z -= mu; x0.w -= mu;
    x1.x -= mu; x1.y -= mu; x1.z -= mu; x1.w -= mu;
    float q = x0.x*x0.x + x0.y*x0.y + x0.z*x0.z + x0.w*x0.w
            + x1.x*x1.x + x1.y*x1.y + x1.z*x1.z + x1.w*x1.w;
#pragma unroll
    for (int o = 16; o > 0; o >>= 1) q += __shfl_xor_sync(0xffffffffu, q, o);
    float r = rsqrtf(q * (1.f / DMc) + 1e-5f);
    x0.x *= r; x0.y *= r; x0.z *= r; x0.w *= r;
    x1.x *= r; x1.y *= r; x1.z *= r; x1.w *= r;
    p[lane] = x0; p[lane + 32] = x1;
}

// ---------------- block reduce (256 threads) ----------------
__device__ __forceinline__ float block_reduce_256(float val, float* sh) {
    int lane = threadIdx.x & 31, w = threadIdx.x >> 5;
#pragma unroll
    for (int o = 16; o > 0; o >>= 1) val += __shfl_down_sync(0xffffffffu, val, o);
    if (lane == 0) sh[w] = val;
    __syncthreads();
    if (w == 0) {
        float v2 = (lane < 8) ? sh[lane] : 0.f;
#pragma unroll
        for (int o = 4; o > 0; o >>= 1) v2 += __shfl_down_sync(0xffffffffu, v2, o);
        if (lane == 0) sh[0] = v2;
    }
    __syncthreads();
    float r = sh[0];
    __syncthreads();
    return r;
}

// ---------------- fused: shift + window context + l2norm + X build (fp16) ----------------
__global__ __launch_bounds__(256)
void shiftx_kernel(const float* __restrict__ theta)
{
    __shared__ float sh[8];
    const int t = blockIdx.x, b = blockIdx.y, d = threadIdx.x;
    float th = fminf(fmaxf(theta[0], -12.f), 12.f);
    float delta = 2.f + 4.f / (1.f + expf(-th));
    float dl = fminf(fmaxf(delta, 0.f), (float)(Tc - 1));
    float nf = floorf(dl);
    float alpha = dl - nf;
    int ni = (int)nf;

    const int lo = max(0, t - 5);
    const float* arow = g_a + (size_t)b * Tc * DMc;
    float sum = 0.f;
    for (int tau = lo; tau <= t; tau++) {
        int i0 = min(max(tau - ni, 0), Tc - 1);
        int i1 = min(i0 + 1, Tc - 1);
        sum += (1.f - alpha) * arow[(size_t)i0 * DMc + d]
             +        alpha  * arow[(size_t)i1 * DMc + d];
    }
    const size_t row = (size_t)b * Tc + t;
    float actx = sum / (float)(t - lo + 1);
    g_actx[row * DMc + d] = actx;

    float vv = g_v[row * DMc + d];
    float ssv = block_reduce_256(vv * vv, sh);
    float ssa = block_reduce_256(actx * actx, sh);
    float vn = vv   / fmaxf(sqrtf(ssv), 1e-8f);
    float an = actx / fmaxf(sqrtf(ssa), 1e-8f);
    size_t base = row * XDIM;
    g_Xh[base + d]           = __float2half(an);
    g_Xh[base + DMc + d]     = __float2half(vn);
    g_Xh[base + 2 * DMc + d] = __float2half(an * vn);
}

// ---------------- finalize ----------------
__global__ __launch_bounds__(256)
void final_kernel(const float* __restrict__ b2, float* __restrict__ out)
{
    const size_t row = blockIdx.x;
    const int d = threadIdx.x;
    float l = b2[0];
#pragma unroll
    for (int p = 0; p < 8; p++) l += g_part[row * 8 + p];
    l = fminf(fmaxf(l, -12.f), 12.f);
    float g = 1.f / (1.f + expf(-l));
    g = fminf(fmaxf(g, 0.05f), 0.95f);
    size_t idx = row * DMc + d;
    out[idx] = g * g_actx[idx] + (1.f - g) * g_v[idx];
}

// ---------------- launch ----------------
extern "C" void kernel_launch(void* const* d_in, const int* in_sizes, int n_in,
                              void* d_out, int out_size)
{
    const float* video = (const float*)d_in[0];
    const float* audio = (const float*)d_in[1];
    const float* Wv    = (const float*)d_in[2];
    const float* bv    = (const float*)d_in[3];
    const float* Wa    = (const float*)d_in[4];
    const float* ba    = (const float*)d_in[5];
    const float* theta = (const float*)d_in[6];
    const float* W1    = (const float*)d_in[7];
    const float* b1    = (const float*)d_in[8];
    const float* W2    = (const float*)d_in[9];
    const float* b2    = (const float*)d_in[10];
    float* out = (float*)d_out;

    float *gv, *ga, *gpart;
    __half *vh, *ah, *xh, *bvw, *baw, *b1w;
    cudaGetSymbolAddress((void**)&gv, g_v);
    cudaGetSymbolAddress((void**)&ga, g_a);
    cudaGetSymbolAddress((void**)&gpart, g_part);
    cudaGetSymbolAddress((void**)&vh, g_Vh);
    cudaGetSymbolAddress((void**)&ah, g_Ah);
    cudaGetSymbolAddress((void**)&xh, g_Xh);
    cudaGetSymbolAddress((void**)&bvw, g_Bv);
    cudaGetSymbolAddress((void**)&baw, g_Ba);
    cudaGetSymbolAddress((void**)&b1w, g_B1);

    cudaFuncSetAttribute(mma_gemm<false>, cudaFuncAttributeMaxDynamicSharedMemorySize, GSM_TOTAL);
    cudaFuncSetAttribute(mma_gemm<true>,  cudaFuncAttributeMaxDynamicSharedMemorySize, GSM_TOTAL);

    // converts
    cvt_act<<<(MROWS * (VDIMc / 4) + 255) / 256, 256>>>((const float4*)video, vh, MROWS * VDIMc / 4);
    cvt_act<<<(MROWS * (ADIMc / 4) + 255) / 256, 256>>>((const float4*)audio, ah, MROWS * ADIMc / 4);
    wcvtT<<<dim3(VDIMc / 32, DMc / 32), 256>>>(Wv, bvw, VDIMc, DMc);
    wcvtT<<<dim3(ADIMc / 32, DMc / 32), 256>>>(Wa, baw, ADIMc, DMc);
    wcvtT<<<dim3(XDIM / 32, HIDc / 32), 256>>>(W1, b1w, XDIM, HIDc);

    // projections
    mma_gemm<false><<<dim3(DMc / 128, MROWS / 128), 256, GSM_TOTAL>>>(
        vh, bvw, bv, nullptr, gv, VDIMc, DMc);
    mma_gemm<false><<<dim3(DMc / 128, MROWS / 128), 256, GSM_TOTAL>>>(
        ah, baw, ba, nullptr, ga, ADIMc, DMc);

    // layernorms (warp-per-row)
    ln8_kernel<<<MROWS / 8, 256>>>(gv);
    ln8_kernel<<<MROWS / 8, 256>>>(ga);

    // fused shift + context + l2norm + X build
    shiftx_kernel<<<dim3(Tc, Bc), 256>>>(theta);

    // gate MLP with fused gelu + W2 reduction
    mma_gemm<true><<<dim3(HIDc / 128, MROWS / 128), 256, GSM_TOTAL>>>(
        xh, b1w, b1, W2, gpart, XDIM, HIDc);

    final_kernel<<<MROWS, 256>>>(b2, out);
}

// round 11
// speedup vs baseline: 5.2630x; 1.0397x over previous
#include <cuda_runtime.h>
#include <cuda_fp16.h>
#include <math.h>
#include <stdint.h>

// ---------------- problem constants ----------------
#define Bc     8
#define Tc     2048
#define VDIMc  1024
#define ADIMc  768
#define DMc    256
#define HIDc   1024
#define MROWS  (Bc * Tc)          // 16384
#define XDIM   (3 * DMc)          // 768

// ---------------- scratch (device globals; no allocation allowed) ----------------
__device__ float g_v   [MROWS * DMc];
__device__ float g_a   [MROWS * DMc];
__device__ float g_actx[MROWS * DMc];
__device__ float g_part[MROWS * 8];

__device__ __half g_Vh[(size_t)MROWS * VDIMc];      // fp16 activations
__device__ __half g_Ah[(size_t)MROWS * ADIMc];
__device__ __half g_Xh[(size_t)MROWS * XDIM];
__device__ __half g_Bv[DMc  * VDIMc];               // fp16 transposed weights [N,K]
__device__ __half g_Ba[DMc  * ADIMc];
__device__ __half g_B1[HIDc * XDIM];

// ---------------- helpers ----------------
__device__ __forceinline__ uint32_t smem_u32(const void* p) {
    uint32_t a;
    asm("{ .reg .u64 t; cvta.to.shared.u64 t, %1; cvt.u32.u64 %0, t; }" : "=r"(a) : "l"(p));
    return a;
}
__device__ __forceinline__ float gelu_exact(float h) {
    return 0.5f * h * (1.f + erff(h * 0.70710678118654752f));
}

#define LDSM4(rg, addr) \
    asm volatile("ldmatrix.sync.aligned.m8n8.x4.shared.b16 {%0,%1,%2,%3}, [%4];" \
        : "=r"((rg)[0]), "=r"((rg)[1]), "=r"((rg)[2]), "=r"((rg)[3]) : "r"(addr))

#define MMA16816(d, a, b) \
    asm volatile("mma.sync.aligned.m16n8k16.row.col.f32.f16.f16.f32 " \
        "{%0,%1,%2,%3}, {%4,%5,%6,%7}, {%8,%9}, {%0,%1,%2,%3};" \
        : "+f"((d)[0]), "+f"((d)[1]), "+f"((d)[2]), "+f"((d)[3]) \
        : "r"((a)[0]), "r"((a)[1]), "r"((a)[2]), "r"((a)[3]), "r"((b)[0]), "r"((b)[1]))

#define CP_ASYNC16(dst, src) \
    asm volatile("cp.async.cg.shared.global [%0], [%1], 16;" :: "r"(dst), "l"(src) : "memory")
#define CP_COMMIT() asm volatile("cp.async.commit_group;" ::: "memory")
#define CP_WAIT1()  asm volatile("cp.async.wait_group 1;" ::: "memory")

// sub-tile: 128 rows x 64 bytes (32 fp16), XOR swizzle on 16B groups
__device__ __forceinline__ uint32_t sw_off(int r, int c16) {
    return (uint32_t)(((r << 6) + (c16 << 4)) ^ ((r & 3) << 4));
}

// ---------------- plain fp16 GEMM body: C[128,128] tile = A @ B^T (+bias) ----------------
// stage = 2 k-chunks {A0,B0,A1,B1}, 8KB sub-tiles -> 32KB/stage
#define STAGES 3
#define STAGEB 32768
static constexpr int SM_EPI    = STAGES * STAGEB;    // 98304
static constexpr int GSM_TOTAL = SM_EPI + 1536;      // 99840

template <bool FUSE>
__device__ __forceinline__ void gemm_body(
    char* smem, const __half* __restrict__ A, const __half* __restrict__ Bm,
    const float* __restrict__ bias, const float* __restrict__ W2,
    float* __restrict__ out, int K, int Ntot, int bx, int by, int nxt)
{
    const uint32_t sbase = smem_u32(smem);
    const int tid  = threadIdx.x;
    const int lane = tid & 31, warp = tid >> 5;
    const int wm = warp >> 2, wn = warp & 3;          // 2 x 4 warp grid (64m x 32n)

    float* sBias = (float*)(smem + SM_EPI);
    float* sW2   = (float*)(smem + SM_EPI + 512);
    float* sRow  = (float*)(smem + SM_EPI + 1024);
    if (tid < 128) {
        sBias[tid] = bias[bx * 128 + tid];
        if (FUSE) { sW2[tid] = W2[bx * 128 + tid]; sRow[tid] = 0.f; }
    }

    const int ni = K >> 6;            // dual-chunk iterations (64 K each)
    const int cr = tid >> 2, cc = tid & 3;

    const __half* Ab = A  + (size_t)(by * 128 + cr) * K + cc * 8;
    const __half* Bb = Bm + (size_t)(bx * 128 + cr) * K + cc * 8;

    float acc[4][4][4];
#pragma unroll
    for (int i = 0; i < 4; i++)
#pragma unroll
        for (int j = 0; j < 4; j++)
#pragma unroll
            for (int q = 0; q < 4; q++) acc[i][j][q] = 0.f;

    auto load_stage = [&](int stage, int it) {
        const uint32_t s0 = sbase + stage * STAGEB;
#pragma unroll
        for (int h = 0; h < 2; h++) {
            const int kofs = (2 * it + h) * 32;
            const __half* a0 = Ab + kofs;
            const __half* b0 = Bb + kofs;
            const uint32_t sA = s0 + h * 16384;
            const uint32_t sB = sA + 8192;
            CP_ASYNC16(sA + sw_off(cr,      cc), a0);
            CP_ASYNC16(sA + sw_off(cr + 64, cc), a0 + (size_t)64 * K);
            CP_ASYNC16(sB + sw_off(cr,      cc), b0);
            CP_ASYNC16(sB + sw_off(cr + 64, cc), b0 + (size_t)64 * K);
        }
    };

    load_stage(0, 0); CP_COMMIT();
    load_stage(1, 1); CP_COMMIT();

    const int arow  = wm * 64 + (lane & 15);
    const int acsel = lane >> 4;
    const int brow  = wn * 32 + (lane & 7) + ((lane >> 4) << 3);
    const int bcsel = (lane >> 3) & 1;

    for (int it = 0; it < ni; it++) {
        CP_WAIT1();
        __syncthreads();

        const int nx = it + 2;
        if (nx < ni) load_stage(nx % STAGES, nx);
        CP_COMMIT();

#pragma unroll
        for (int h = 0; h < 2; h++) {
            const uint32_t sA = sbase + (it % STAGES) * STAGEB + h * 16384;
            const uint32_t sB = sA + 8192;
#pragma unroll
            for (int ks = 0; ks < 2; ks++) {
                uint32_t afr[4][4], bfr[2][4];
#pragma unroll
                for (int mt = 0; mt < 4; mt++)
                    LDSM4(afr[mt], sA + sw_off(arow + mt * 16, ks * 2 + acsel));
#pragma unroll
                for (int nb = 0; nb < 2; nb++)
                    LDSM4(bfr[nb], sB + sw_off(brow + nb * 16, ks * 2 + bcsel));
#pragma unroll
                for (int mt = 0; mt < 4; mt++) {
#pragma unroll
                    for (int n8 = 0; n8 < 4; n8++) {
                        uint32_t bb[2] = { bfr[n8 >> 1][(n8 & 1) * 2], bfr[n8 >> 1][(n8 & 1) * 2 + 1] };
                        MMA16816(acc[mt][n8], afr[mt], bb);
                    }
                }
            }
        }
        // no trailing sync: next iteration's leading sync protects the stage
    }

    // ---- epilogue ----
    if (!FUSE) {
#pragma unroll
        for (int mt = 0; mt < 4; mt++) {
            const int row = by * 128 + wm * 64 + mt * 16 + (lane >> 2);
#pragma unroll
            for (int n8 = 0; n8 < 4; n8++) {
                const int lc  = wn * 32 + n8 * 8 + (lane & 3) * 2;
                const int col = bx * 128 + lc;
                float2 v0 = { acc[mt][n8][0] + sBias[lc], acc[mt][n8][1] + sBias[lc + 1] };
                float2 v1 = { acc[mt][n8][2] + sBias[lc], acc[mt][n8][3] + sBias[lc + 1] };
                *reinterpret_cast<float2*>(out + (size_t)row * Ntot + col)       = v0;
                *reinterpret_cast<float2*>(out + (size_t)(row + 8) * Ntot + col) = v1;
            }
        }
    } else {
#pragma unroll
        for (int mt = 0; mt < 4; mt++) {
            float pA = 0.f, pB = 0.f;
#pragma unroll
            for (int n8 = 0; n8 < 4; n8++) {
                const int lc = wn * 32 + n8 * 8 + (lane & 3) * 2;
                pA += gelu_exact(acc[mt][n8][0] + sBias[lc])     * sW2[lc];
                pA += gelu_exact(acc[mt][n8][1] + sBias[lc + 1]) * sW2[lc + 1];
                pB += gelu_exact(acc[mt][n8][2] + sBias[lc])     * sW2[lc];
                pB += gelu_exact(acc[mt][n8][3] + sBias[lc + 1]) * sW2[lc + 1];
            }
            pA += __shfl_xor_sync(0xffffffffu, pA, 1);
            pA += __shfl_xor_sync(0xffffffffu, pA, 2);
            pB += __shfl_xor_sync(0xffffffffu, pB, 1);
            pB += __shfl_xor_sync(0xffffffffu, pB, 2);
            if ((lane & 3) == 0) {
                atomicAdd(&sRow[wm * 64 + mt * 16 + (lane >> 2)],     pA);
                atomicAdd(&sRow[wm * 64 + mt * 16 + (lane >> 2) + 8], pB);
            }
        }
        __syncthreads();
        if (tid < 128)
            out[(size_t)(by * 128 + tid) * nxt + bx] = sRow[tid];
    }
}

// merged projection GEMM: z=0 -> video (K=VDIMc), z=1 -> audio (K=ADIMc)
__global__ void __launch_bounds__(256, 2)
proj_gemm(const __half* __restrict__ Av, const __half* __restrict__ Bv,
          const float* __restrict__ bv, float* __restrict__ ov,
          const __half* __restrict__ Aa, const __half* __restrict__ Ba,
          const float* __restrict__ ba, float* __restrict__ oa)
{
    extern __shared__ char smem[];
    if (blockIdx.z == 0)
        gemm_body<false>(smem, Av, Bv, bv, nullptr, ov, VDIMc, DMc,
                         blockIdx.x, blockIdx.y, 0);
    else
        gemm_body<false>(smem, Aa, Ba, ba, nullptr, oa, ADIMc, DMc,
                         blockIdx.x, blockIdx.y, 0);
}

// gate MLP GEMM with fused gelu + W2 partial reduction
__global__ void __launch_bounds__(256, 2)
mlp_gemm(const __half* __restrict__ A, const __half* __restrict__ Bm,
         const float* __restrict__ bias, const float* __restrict__ W2,
         float* __restrict__ out)
{
    extern __shared__ char smem[];
    gemm_body<true>(smem, A, Bm, bias, W2, out, XDIM, HIDc,
                    blockIdx.x, blockIdx.y, gridDim.x);
}

// ---------------- activation convert: f32 -> fp16 ----------------
__global__ __launch_bounds__(256)
void cvt_act(const float4* __restrict__ X, __half* __restrict__ dst, int n4)
{
    int i = blockIdx.x * 256 + threadIdx.x;
    if (i >= n4) return;
    float4 x = X[i];
    ushort4 v;
    v.x = __half_as_ushort(__float2half(x.x));
    v.y = __half_as_ushort(__float2half(x.y));
    v.z = __half_as_ushort(__float2half(x.z));
    v.w = __half_as_ushort(__float2half(x.w));
    *reinterpret_cast<ushort4*>(dst + 4 * (size_t)i) = v;
}

// ---------------- tiled weight convert+transpose: W[K,N] -> [N,K] fp16 ----------------
__global__ __launch_bounds__(256)
void wcvtT(const float* __restrict__ W, __half* __restrict__ dst, int K, int N)
{
    __shared__ float tile[32][33];
    const int k0 = blockIdx.x * 32, n0 = blockIdx.y * 32;
    const int tx = threadIdx.x & 31, ty8 = threadIdx.x >> 5;
#pragma unroll
    for (int i = 0; i < 4; i++) {
        int ty = ty8 + i * 8;
        tile[ty][tx] = W[(size_t)(k0 + ty) * N + n0 + tx];
    }
    __syncthreads();
#pragma unroll
    for (int i = 0; i < 4; i++) {
        int ny = ty8 + i * 8;
        dst[(size_t)(n0 + ny) * K + k0 + tx] = __float2half(tile[tx][ny]);
    }
}

// ---------------- warp-per-row LayerNorm (DM=256), 8 rows/block, both tensors ----------------
__global__ __launch_bounds__(256)
void ln8_kernel()
{
    const int lane = threadIdx.x & 31, w = threadIdx.x >> 5;
    float* X = (blockIdx.y == 0) ? g_v : g_a;
    const size_t row = (size_t)blockIdx.x * 8 + w;
    float4* p = reinterpret_cast<float4*>(X + row * DMc);
    float4 x0 = p[lane], x1 = p[lane + 32];
    float s = x0.x + x0.y + x0.z + x0.w + x1.x + x1.y + x1.z + x1.w;
#pragma unroll
    for (int o = 16; o > 0; o >>= 1) s += __shfl_xor_sync(0xffffffffu, s, o);
    float mu = s * (1.f / DMc);
    x0.x -= mu; x0.y -= mu; x0.z -= mu; x0.w -= mu;
    x1.x -= mu; x1.y -= mu; x1.z -= mu; x1.w -= mu;
    float q = x0.x*x0.x + x0.y*x0.y + x0.z*x0.z + x0.w*x0.w
            + x1.x*x1.x + x1.y*x1.y + x1.z*x1.z + x1.w*x1.w;
#pragma unroll
    for (int o = 16; o > 0; o >>= 1) q += __shfl_xor_sync(0xffffffffu, q, o);
    float r = rsqrtf(q * (1.f / DMc) + 1e-5f);
    x0.x *= r; x0.y *= r; x0.z *= r; x0.w *= r;
    x1.x *= r; x1.y *= r; x1.z *= r; x1.w *= r;
    p[lane] = x0; p[lane + 32] = x1;
}

// ---------------- block reduce (256 threads) ----------------
__device__ __forceinline__ float block_reduce_256(float val, float* sh) {
    int lane = threadIdx.x & 31, w = threadIdx.x >> 5;
#pragma unroll
    for (int o = 16; o > 0; o >>= 1) val += __shfl_down_sync(0xffffffffu, val, o);
    if (lane == 0) sh[w] = val;
    __syncthreads();
    if (w == 0) {
        float v2 = (lane < 8) ? sh[lane] : 0.f;
#pragma unroll
        for (int o = 4; o > 0; o >>= 1) v2 += __shfl_down_sync(0xffffffffu, v2, o);
        if (lane == 0) sh[0] = v2;
    }
    __syncthreads();
    float r = sh[0];
    __syncthreads();
    return r;
}

// ---------------- fused: shift + window context + l2norm + X build (fp16) ----------------
__global__ __launch_bounds__(256)
void shiftx_kernel(const float* __restrict__ theta)
{
    __shared__ float sh[8];
    const int t = blockIdx.x, b = blockIdx.y, d = threadIdx.x;
    float th = fminf(fmaxf(theta[0], -12.f), 12.f);
    float delta = 2.f + 4.f / (1.f + expf(-th));
    float dl = fminf(fmaxf(delta, 0.f), (float)(Tc - 1));
    float nf = floorf(dl);
    float alpha = dl - nf;
    int ni = (int)nf;

    const int lo = max(0, t - 5);
    const float* arow = g_a + (size_t)b * Tc * DMc;
    float sum = 0.f;
    for (int tau = lo; tau <= t; tau++) {
        int i0 = min(max(tau - ni, 0), Tc - 1);
        int i1 = min(i0 + 1, Tc - 1);
        sum += (1.f - alpha) * arow[(size_t)i0 * DMc + d]
             +        alpha  * arow[(size_t)i1 * DMc + d];
    }
    const size_t row = (size_t)b * Tc + t;
    float actx = sum / (float)(t - lo + 1);
    g_actx[row * DMc + d] = actx;

    float vv = g_v[row * DMc + d];
    float ssv = block_reduce_256(vv * vv, sh);
    float ssa = block_reduce_256(actx * actx, sh);
    float vn = vv   / fmaxf(sqrtf(ssv), 1e-8f);
    float an = actx / fmaxf(sqrtf(ssa), 1e-8f);
    size_t base = row * XDIM;
    g_Xh[base + d]           = __float2half(an);
    g_Xh[base + DMc + d]     = __float2half(vn);
    g_Xh[base + 2 * DMc + d] = __float2half(an * vn);
}

// ---------------- finalize: warp per row, 8 rows/block ----------------
__global__ __launch_bounds__(256)
void final_kernel(const float* __restrict__ b2, float* __restrict__ out)
{
    const int lane = threadIdx.x & 31, w = threadIdx.x >> 5;
    const size_t row = (size_t)blockIdx.x * 8 + w;
    float l = b2[0];
#pragma unroll
    for (int p = 0; p < 8; p++) l += g_part[row * 8 + p];
    l = fminf(fmaxf(l, -12.f), 12.f);
    float g = 1.f / (1.f + expf(-l));
    g = fminf(fmaxf(g, 0.05f), 0.95f);
    const float4* pa = reinterpret_cast<const float4*>(g_actx + row * DMc);
    const float4* pv = reinterpret_cast<const float4*>(g_v    + row * DMc);
    float4* po = reinterpret_cast<float4*>(out + row * DMc);
#pragma unroll
    for (int h = 0; h < 2; h++) {
        float4 a4 = pa[lane + h * 32], v4 = pv[lane + h * 32], o4;
        o4.x = g * a4.x + (1.f - g) * v4.x;
        o4.y = g * a4.y + (1.f - g) * v4.y;
        o4.z = g * a4.z + (1.f - g) * v4.z;
        o4.w = g * a4.w + (1.f - g) * v4.w;
        po[lane + h * 32] = o4;
    }
}

// ---------------- launch ----------------
extern "C" void kernel_launch(void* const* d_in, const int* in_sizes, int n_in,
                              void* d_out, int out_size)
{
    const float* video = (const float*)d_in[0];
    const float* audio = (const float*)d_in[1];
    const float* Wv    = (const float*)d_in[2];
    const float* bv    = (const float*)d_in[3];
    const float* Wa    = (const float*)d_in[4];
    const float* ba    = (const float*)d_in[5];
    const float* theta = (const float*)d_in[6];
    const float* W1    = (const float*)d_in[7];
    const float* b1    = (const float*)d_in[8];
    const float* W2    = (const float*)d_in[9];
    const float* b2    = (const float*)d_in[10];
    float* out = (float*)d_out;

    float *gv, *ga, *gpart;
    __half *vh, *ah, *xh, *bvw, *baw, *b1w;
    cudaGetSymbolAddress((void**)&gv, g_v);
    cudaGetSymbolAddress((void**)&ga, g_a);
    cudaGetSymbolAddress((void**)&gpart, g_part);
    cudaGetSymbolAddress((void**)&vh, g_Vh);
    cudaGetSymbolAddress((void**)&ah, g_Ah);
    cudaGetSymbolAddress((void**)&xh, g_Xh);
    cudaGetSymbolAddress((void**)&bvw, g_Bv);
    cudaGetSymbolAddress((void**)&baw, g_Ba);
    cudaGetSymbolAddress((void**)&b1w, g_B1);

    cudaFuncSetAttribute(proj_gemm, cudaFuncAttributeMaxDynamicSharedMemorySize, GSM_TOTAL);
    cudaFuncSetAttribute(mlp_gemm,  cudaFuncAttributeMaxDynamicSharedMemorySize, GSM_TOTAL);

    // converts
    cvt_act<<<(MROWS * (VDIMc / 4) + 255) / 256, 256>>>((const float4*)video, vh, MROWS * VDIMc / 4);
    cvt_act<<<(MROWS * (ADIMc / 4) + 255) / 256, 256>>>((const float4*)audio, ah, MROWS * ADIMc / 4);
    wcvtT<<<dim3(VDIMc / 32, DMc / 32), 256>>>(Wv, bvw, VDIMc, DMc);
    wcvtT<<<dim3(ADIMc / 32, DMc / 32), 256>>>(Wa, baw, ADIMc, DMc);
    wcvtT<<<dim3(XDIM / 32, HIDc / 32), 256>>>(W1, b1w, XDIM, HIDc);

    // merged projections (z=0 video, z=1 audio)
    proj_gemm<<<dim3(DMc / 128, MROWS / 128, 2), 256, GSM_TOTAL>>>(
        vh, bvw, bv, gv, ah, baw, ba, ga);

    // layernorms (warp-per-row, both tensors in one launch)
    ln8_kernel<<<dim3(MROWS / 8, 2), 256>>>();

    // fused shift + context + l2norm + X build
    shiftx_kernel<<<dim3(Tc, Bc), 256>>>(theta);

    // gate MLP with fused gelu + W2 reduction
    mlp_gemm<<<dim3(HIDc / 128, MROWS / 128), 256, GSM_TOTAL>>>(
        xh, b1w, b1, W2, gpart);

    final_kernel<<<MROWS / 8, 256>>>(b2, out);
}

// round 12
// speedup vs baseline: 5.9097x; 1.1229x over previous
#include <cuda_runtime.h>
#include <cuda_fp16.h>
#include <math.h>
#include <stdint.h>

// ---------------- problem constants ----------------
#define Bc     8
#define Tc     2048
#define VDIMc  1024
#define ADIMc  768
#define DMc    256
#define HIDc   1024
#define MROWS  (Bc * Tc)          // 16384
#define XDIM   (3 * DMc)          // 768

// ---------------- scratch (device globals; no allocation allowed) ----------------
__device__ float g_v   [MROWS * DMc];
__device__ float g_a   [MROWS * DMc];
__device__ float g_actx[MROWS * DMc];
__device__ float g_part[MROWS * 8];

__device__ __half g_Vh[(size_t)MROWS * VDIMc];      // fp16 activations
__device__ __half g_Ah[(size_t)MROWS * ADIMc];
__device__ __half g_Xh[(size_t)MROWS * XDIM];
__device__ __half g_Bv[DMc  * VDIMc];               // fp16 transposed weights [N,K]
__device__ __half g_Ba[DMc  * ADIMc];
__device__ __half g_B1[HIDc * XDIM];

// ---------------- helpers ----------------
__device__ __forceinline__ uint32_t smem_u32(const void* p) {
    uint32_t a;
    asm("{ .reg .u64 t; cvta.to.shared.u64 t, %1; cvt.u32.u64 %0, t; }" : "=r"(a) : "l"(p));
    return a;
}
__device__ __forceinline__ float gelu_exact(float h) {
    return 0.5f * h * (1.f + erff(h * 0.70710678118654752f));
}

#define LDSM4(rg, addr) \
    asm volatile("ldmatrix.sync.aligned.m8n8.x4.shared.b16 {%0,%1,%2,%3}, [%4];" \
        : "=r"((rg)[0]), "=r"((rg)[1]), "=r"((rg)[2]), "=r"((rg)[3]) : "r"(addr))

#define MMA16816(d, a, b) \
    asm volatile("mma.sync.aligned.m16n8k16.row.col.f32.f16.f16.f32 " \
        "{%0,%1,%2,%3}, {%4,%5,%6,%7}, {%8,%9}, {%0,%1,%2,%3};" \
        : "+f"((d)[0]), "+f"((d)[1]), "+f"((d)[2]), "+f"((d)[3]) \
        : "r"((a)[0]), "r"((a)[1]), "r"((a)[2]), "r"((a)[3]), "r"((b)[0]), "r"((b)[1]))

#define CP_ASYNC16(dst, src) \
    asm volatile("cp.async.cg.shared.global [%0], [%1], 16;" :: "r"(dst), "l"(src) : "memory")
#define CP_COMMIT() asm volatile("cp.async.commit_group;" ::: "memory")
#define CP_WAIT1()  asm volatile("cp.async.wait_group 1;" ::: "memory")

// sub-tile: 128 rows x 64 bytes (32 fp16), XOR swizzle on 16B groups
__device__ __forceinline__ uint32_t sw_off(int r, int c16) {
    return (uint32_t)(((r << 6) + (c16 << 4)) ^ ((r & 3) << 4));
}

// ---------------- plain fp16 GEMM body: C[128,128] tile = A @ B^T (+bias) ----------------
// stage = 2 k-chunks {A0,B0,A1,B1}, 8KB sub-tiles -> 32KB/stage
#define STAGES 3
#define STAGEB 32768
static constexpr int SM_EPI    = STAGES * STAGEB;    // 98304
static constexpr int GSM_TOTAL = SM_EPI + 1536;      // 99840

template <bool FUSE>
__device__ __forceinline__ void gemm_body(
    char* smem, const __half* __restrict__ A, const __half* __restrict__ Bm,
    const float* __restrict__ bias, const float* __restrict__ W2,
    float* __restrict__ out, int K, int Ntot, int bx, int by, int nxt)
{
    const uint32_t sbase = smem_u32(smem);
    const int tid  = threadIdx.x;
    const int lane = tid & 31, warp = tid >> 5;
    const int wm = warp >> 2, wn = warp & 3;          // 2 x 4 warp grid (64m x 32n)

    float* sBias = (float*)(smem + SM_EPI);
    float* sW2   = (float*)(smem + SM_EPI + 512);
    float* sRow  = (float*)(smem + SM_EPI + 1024);
    if (tid < 128) {
        sBias[tid] = bias[bx * 128 + tid];
        if (FUSE) { sW2[tid] = W2[bx * 128 + tid]; sRow[tid] = 0.f; }
    }

    const int ni = K >> 6;            // dual-chunk iterations (64 K each)
    const int cr = tid >> 2, cc = tid & 3;

    const __half* Ab = A  + (size_t)(by * 128 + cr) * K + cc * 8;
    const __half* Bb = Bm + (size_t)(bx * 128 + cr) * K + cc * 8;

    float acc[4][4][4];
#pragma unroll
    for (int i = 0; i < 4; i++)
#pragma unroll
        for (int j = 0; j < 4; j++)
#pragma unroll
            for (int q = 0; q < 4; q++) acc[i][j][q] = 0.f;

    auto load_stage = [&](int stage, int it) {
        const uint32_t s0 = sbase + stage * STAGEB;
#pragma unroll
        for (int h = 0; h < 2; h++) {
            const int kofs = (2 * it + h) * 32;
            const __half* a0 = Ab + kofs;
            const __half* b0 = Bb + kofs;
            const uint32_t sA = s0 + h * 16384;
            const uint32_t sB = sA + 8192;
            CP_ASYNC16(sA + sw_off(cr,      cc), a0);
            CP_ASYNC16(sA + sw_off(cr + 64, cc), a0 + (size_t)64 * K);
            CP_ASYNC16(sB + sw_off(cr,      cc), b0);
            CP_ASYNC16(sB + sw_off(cr + 64, cc), b0 + (size_t)64 * K);
        }
    };

    load_stage(0, 0); CP_COMMIT();
    load_stage(1, 1); CP_COMMIT();

    const int arow  = wm * 64 + (lane & 15);
    const int acsel = lane >> 4;
    const int brow  = wn * 32 + (lane & 7) + ((lane >> 4) << 3);
    const int bcsel = (lane >> 3) & 1;

    for (int it = 0; it < ni; it++) {
        CP_WAIT1();
        __syncthreads();

        const int nx = it + 2;
        if (nx < ni) load_stage(nx % STAGES, nx);
        CP_COMMIT();

#pragma unroll
        for (int h = 0; h < 2; h++) {
            const uint32_t sA = sbase + (it % STAGES) * STAGEB + h * 16384;
            const uint32_t sB = sA + 8192;
#pragma unroll
            for (int ks = 0; ks < 2; ks++) {
                uint32_t afr[4][4], bfr[2][4];
#pragma unroll
                for (int mt = 0; mt < 4; mt++)
                    LDSM4(afr[mt], sA + sw_off(arow + mt * 16, ks * 2 + acsel));
#pragma unroll
                for (int nb = 0; nb < 2; nb++)
                    LDSM4(bfr[nb], sB + sw_off(brow + nb * 16, ks * 2 + bcsel));
#pragma unroll
                for (int mt = 0; mt < 4; mt++) {
#pragma unroll
                    for (int n8 = 0; n8 < 4; n8++) {
                        uint32_t bb[2] = { bfr[n8 >> 1][(n8 & 1) * 2], bfr[n8 >> 1][(n8 & 1) * 2 + 1] };
                        MMA16816(acc[mt][n8], afr[mt], bb);
                    }
                }
            }
        }
        // no trailing sync: next iteration's leading sync protects the stage
    }

    // ---- epilogue ----
    if (!FUSE) {
#pragma unroll
        for (int mt = 0; mt < 4; mt++) {
            const int row = by * 128 + wm * 64 + mt * 16 + (lane >> 2);
#pragma unroll
            for (int n8 = 0; n8 < 4; n8++) {
                const int lc  = wn * 32 + n8 * 8 + (lane & 3) * 2;
                const int col = bx * 128 + lc;
                float2 v0 = { acc[mt][n8][0] + sBias[lc], acc[mt][n8][1] + sBias[lc + 1] };
                float2 v1 = { acc[mt][n8][2] + sBias[lc], acc[mt][n8][3] + sBias[lc + 1] };
                *reinterpret_cast<float2*>(out + (size_t)row * Ntot + col)       = v0;
                *reinterpret_cast<float2*>(out + (size_t)(row + 8) * Ntot + col) = v1;
            }
        }
    } else {
#pragma unroll
        for (int mt = 0; mt < 4; mt++) {
            float pA = 0.f, pB = 0.f;
#pragma unroll
            for (int n8 = 0; n8 < 4; n8++) {
                const int lc = wn * 32 + n8 * 8 + (lane & 3) * 2;
                pA += gelu_exact(acc[mt][n8][0] + sBias[lc])     * sW2[lc];
                pA += gelu_exact(acc[mt][n8][1] + sBias[lc + 1]) * sW2[lc + 1];
                pB += gelu_exact(acc[mt][n8][2] + sBias[lc])     * sW2[lc];
                pB += gelu_exact(acc[mt][n8][3] + sBias[lc + 1]) * sW2[lc + 1];
            }
            pA += __shfl_xor_sync(0xffffffffu, pA, 1);
            pA += __shfl_xor_sync(0xffffffffu, pA, 2);
            pB += __shfl_xor_sync(0xffffffffu, pB, 1);
            pB += __shfl_xor_sync(0xffffffffu, pB, 2);
            if ((lane & 3) == 0) {
                atomicAdd(&sRow[wm * 64 + mt * 16 + (lane >> 2)],     pA);
                atomicAdd(&sRow[wm * 64 + mt * 16 + (lane >> 2) + 8], pB);
            }
        }
        __syncthreads();
        if (tid < 128)
            out[(size_t)(by * 128 + tid) * nxt + bx] = sRow[tid];
    }
}

// merged projection GEMM: z=0 -> video (K=VDIMc), z=1 -> audio (K=ADIMc)
__global__ void __launch_bounds__(256, 2)
proj_gemm(const __half* __restrict__ Av, const __half* __restrict__ Bv,
          const float* __restrict__ bv, float* __restrict__ ov,
          const __half* __restrict__ Aa, const __half* __restrict__ Ba,
          const float* __restrict__ ba, float* __restrict__ oa)
{
    extern __shared__ char smem[];
    if (blockIdx.z == 0)
        gemm_body<false>(smem, Av, Bv, bv, nullptr, ov, VDIMc, DMc,
                         blockIdx.x, blockIdx.y, 0);
    else
        gemm_body<false>(smem, Aa, Ba, ba, nullptr, oa, ADIMc, DMc,
                         blockIdx.x, blockIdx.y, 0);
}

// gate MLP GEMM with fused gelu + W2 partial reduction
__global__ void __launch_bounds__(256, 2)
mlp_gemm(const __half* __restrict__ A, const __half* __restrict__ Bm,
         const float* __restrict__ bias, const float* __restrict__ W2,
         float* __restrict__ out)
{
    extern __shared__ char smem[];
    gemm_body<true>(smem, A, Bm, bias, W2, out, XDIM, HIDc,
                    blockIdx.x, blockIdx.y, gridDim.x);
}

// ---------------- mega prep: activation converts + weight transposes, one launch ----------
#define NB_V (MROWS * VDIMc / 4 / 256)    // 16384
#define NB_A (MROWS * ADIMc / 4 / 256)    // 12288
#define NB_WV ((VDIMc / 32) * (DMc / 32))   // 256
#define NB_WA ((ADIMc / 32) * (DMc / 32))   // 192
#define NB_W1 ((XDIM / 32) * (HIDc / 32))   // 768
#define NB_TOTAL (NB_V + NB_A + NB_WV + NB_WA + NB_W1)

__device__ __forceinline__ void cvt_body(const float4* __restrict__ X,
                                         __half* __restrict__ dst, int i)
{
    float4 x = X[i];
    ushort4 v;
    v.x = __half_as_ushort(__float2half(x.x));
    v.y = __half_as_ushort(__float2half(x.y));
    v.z = __half_as_ushort(__float2half(x.z));
    v.w = __half_as_ushort(__float2half(x.w));
    *reinterpret_cast<ushort4*>(dst + 4 * (size_t)i) = v;
}

__device__ __forceinline__ void wcvtT_body(float (*tile)[33],
                                           const float* __restrict__ W,
                                           __half* __restrict__ dst,
                                           int K, int N, int bxk, int byn)
{
    const int k0 = bxk * 32, n0 = byn * 32;
    const int tx = threadIdx.x & 31, ty8 = threadIdx.x >> 5;
#pragma unroll
    for (int i = 0; i < 4; i++) {
        int ty = ty8 + i * 8;
        tile[ty][tx] = W[(size_t)(k0 + ty) * N + n0 + tx];
    }
    __syncthreads();
#pragma unroll
    for (int i = 0; i < 4; i++) {
        int ny = ty8 + i * 8;
        dst[(size_t)(n0 + ny) * K + k0 + tx] = __float2half(tile[tx][ny]);
    }
}

__global__ __launch_bounds__(256)
void prep_kernel(const float4* __restrict__ video, const float4* __restrict__ audio,
                 const float* __restrict__ Wv, const float* __restrict__ Wa,
                 const float* __restrict__ W1,
                 __half* __restrict__ vh, __half* __restrict__ ah,
                 __half* __restrict__ bvw, __half* __restrict__ baw,
                 __half* __restrict__ b1w)
{
    __shared__ float tile[32][33];
    const int bid = blockIdx.x;
    if (bid < NB_V) {
        cvt_body(video, vh, bid * 256 + threadIdx.x);
    } else if (bid < NB_V + NB_A) {
        cvt_body(audio, ah, (bid - NB_V) * 256 + threadIdx.x);
    } else if (bid < NB_V + NB_A + NB_WV) {
        int j = bid - (NB_V + NB_A);
        wcvtT_body(tile, Wv, bvw, VDIMc, DMc, j % (VDIMc / 32), j / (VDIMc / 32));
    } else if (bid < NB_V + NB_A + NB_WV + NB_WA) {
        int j = bid - (NB_V + NB_A + NB_WV);
        wcvtT_body(tile, Wa, baw, ADIMc, DMc, j % (ADIMc / 32), j / (ADIMc / 32));
    } else {
        int j = bid - (NB_V + NB_A + NB_WV + NB_WA);
        wcvtT_body(tile, W1, b1w, XDIM, HIDc, j % (XDIM / 32), j / (XDIM / 32));
    }
}

// ---------------- warp-per-row LayerNorm (DM=256), 8 rows/block, both tensors ----------------
__global__ __launch_bounds__(256)
void ln8_kernel()
{
    const int lane = threadIdx.x & 31, w = threadIdx.x >> 5;
    float* X = (blockIdx.y == 0) ? g_v : g_a;
    const size_t row = (size_t)blockIdx.x * 8 + w;
    float4* p = reinterpret_cast<float4*>(X + row * DMc);
    float4 x0 = p[lane], x1 = p[lane + 32];
    float s = x0.x + x0.y + x0.z + x0.w + x1.x + x1.y + x1.z + x1.w;
#pragma unroll
    for (int o = 16; o > 0; o >>= 1) s += __shfl_xor_sync(0xffffffffu, s, o);
    float mu = s * (1.f / DMc);
    x0.x -= mu; x0.y -= mu; x0.z -= mu; x0.w -= mu;
    x1.x -= mu; x1.y -= mu; x1.z -= mu; x1.w -= mu;
    float q = x0.x*x0.x + x0.y*x0.y + x0.z*x0.z + x0.w*x0.w
            + x1.x*x1.x + x1.y*x1.y + x1.z*x1.z + x1.w*x1.w;
#pragma unroll
    for (int o = 16; o > 0; o >>= 1) q += __shfl_xor_sync(0xffffffffu, q, o);
    float r = rsqrtf(q * (1.f / DMc) + 1e-5f);
    x0.x *= r; x0.y *= r; x0.z *= r; x0.w *= r;
    x1.x *= r; x1.y *= r; x1.z *= r; x1.w *= r;
    p[lane] = x0; p[lane + 32] = x1;
}

// ---------------- warp-per-row shift + window + l2norm + X build ----------------
// 8 (b,t) rows per block, one warp each; lane owns 8 d's; zero block barriers.
__global__ __launch_bounds__(256)
void shiftx_kernel(const float* __restrict__ theta)
{
    const int lane = threadIdx.x & 31, w = threadIdx.x >> 5;
    const size_t row = (size_t)blockIdx.x * 8 + w;        // 0..16383
    const int b = (int)(row >> 11), t = (int)(row & (Tc - 1));

    float th = fminf(fmaxf(theta[0], -12.f), 12.f);
    float delta = 2.f + 4.f / (1.f + expf(-th));
    float dl = fminf(fmaxf(delta, 0.f), (float)(Tc - 1));
    float nf = floorf(dl);
    float alpha = dl - nf;
    int ni = (int)nf;

    const int lo = max(0, t - 5);
    const float* abase = g_a + (size_t)b * Tc * DMc;
    const int d0 = lane * 8;          // 2 float4

    float sum[8], cur[8], nxt[8];
#pragma unroll
    for (int j = 0; j < 8; j++) sum[j] = 0.f;

    auto loadrow = [&](int r, float* dst) {
        const float4* p = reinterpret_cast<const float4*>(abase + (size_t)r * DMc + d0);
        float4 a = p[0], c = p[1];
        dst[0] = a.x; dst[1] = a.y; dst[2] = a.z; dst[3] = a.w;
        dst[4] = c.x; dst[5] = c.y; dst[6] = c.z; dst[7] = c.w;
    };

    int pi = -9999;
    for (int tau = lo; tau <= t; tau++) {
        int i0 = min(max(tau - ni, 0), Tc - 1);
        int i1 = min(i0 + 1, Tc - 1);
        if (i0 != pi) loadrow(i0, cur);
        loadrow(i1, nxt);
#pragma unroll
        for (int j = 0; j < 8; j++)
            sum[j] += (1.f - alpha) * cur[j] + alpha * nxt[j];
#pragma unroll
        for (int j = 0; j < 8; j++) cur[j] = nxt[j];
        pi = i1;
    }

    const float inv = 1.f / (float)(t - lo + 1);
    float actx[8];
#pragma unroll
    for (int j = 0; j < 8; j++) actx[j] = sum[j] * inv;

    // store g_actx
    {
        float4* po = reinterpret_cast<float4*>(g_actx + row * DMc + d0);
        po[0] = make_float4(actx[0], actx[1], actx[2], actx[3]);
        po[1] = make_float4(actx[4], actx[5], actx[6], actx[7]);
    }

    // load v, compute squared norms via warp reduce
    float vv[8];
    {
        const float4* pv = reinterpret_cast<const float4*>(g_v + row * DMc + d0);
        float4 a = pv[0], c = pv[1];
        vv[0] = a.x; vv[1] = a.y; vv[2] = a.z; vv[3] = a.w;
        vv[4] = c.x; vv[5] = c.y; vv[6] = c.z; vv[7] = c.w;
    }
    float ssv = 0.f, ssa = 0.f;
#pragma unroll
    for (int j = 0; j < 8; j++) { ssv += vv[j] * vv[j]; ssa += actx[j] * actx[j]; }
#pragma unroll
    for (int o = 16; o > 0; o >>= 1) {
        ssv += __shfl_xor_sync(0xffffffffu, ssv, o);
        ssa += __shfl_xor_sync(0xffffffffu, ssa, o);
    }
    const float rv = 1.f / fmaxf(sqrtf(ssv), 1e-8f);
    const float ra = 1.f / fmaxf(sqrtf(ssa), 1e-8f);

    __half h8[8];
    const size_t base = row * XDIM;
#pragma unroll
    for (int j = 0; j < 8; j++) h8[j] = __float2half(actx[j] * ra);
    *reinterpret_cast<uint4*>(g_Xh + base + d0) = *reinterpret_cast<uint4*>(h8);
#pragma unroll
    for (int j = 0; j < 8; j++) h8[j] = __float2half(vv[j] * rv);
    *reinterpret_cast<uint4*>(g_Xh + base + DMc + d0) = *reinterpret_cast<uint4*>(h8);
#pragma unroll
    for (int j = 0; j < 8; j++) h8[j] = __float2half((actx[j] * ra) * (vv[j] * rv));
    *reinterpret_cast<uint4*>(g_Xh + base + 2 * DMc + d0) = *reinterpret_cast<uint4*>(h8);
}

// ---------------- finalize: warp per row, 8 rows/block ----------------
__global__ __launch_bounds__(256)
void final_kernel(const float* __restrict__ b2, float* __restrict__ out)
{
    const int lane = threadIdx.x & 31, w = threadIdx.x >> 5;
    const size_t row = (size_t)blockIdx.x * 8 + w;
    float l = b2[0];
#pragma unroll
    for (int p = 0; p < 8; p++) l += g_part[row * 8 + p];
    l = fminf(fmaxf(l, -12.f), 12.f);
    float g = 1.f / (1.f + expf(-l));
    g = fminf(fmaxf(g, 0.05f), 0.95f);
    const float4* pa = reinterpret_cast<const float4*>(g_actx + row * DMc);
    const float4* pv = reinterpret_cast<const float4*>(g_v    + row * DMc);
    float4* po = reinterpret_cast<float4*>(out + row * DMc);
#pragma unroll
    for (int h = 0; h < 2; h++) {
        float4 a4 = pa[lane + h * 32], v4 = pv[lane + h * 32], o4;
        o4.x = g * a4.x + (1.f - g) * v4.x;
        o4.y = g * a4.y + (1.f - g) * v4.y;
        o4.z = g * a4.z + (1.f - g) * v4.z;
        o4.w = g * a4.w + (1.f - g) * v4.w;
        po[lane + h * 32] = o4;
    }
}

// ---------------- launch ----------------
extern "C" void kernel_launch(void* const* d_in, const int* in_sizes, int n_in,
                              void* d_out, int out_size)
{
    const float* video = (const float*)d_in[0];
    const float* audio = (const float*)d_in[1];
    const float* Wv    = (const float*)d_in[2];
    const float* bv    = (const float*)d_in[3];
    const float* Wa    = (const float*)d_in[4];
    const float* ba    = (const float*)d_in[5];
    const float* theta = (const float*)d_in[6];
    const float* W1    = (const float*)d_in[7];
    const float* b1    = (const float*)d_in[8];
    const float* W2    = (const float*)d_in[9];
    const float* b2    = (const float*)d_in[10];
    float* out = (float*)d_out;

    float *gv, *ga, *gpart;
    __half *vh, *ah, *xh, *bvw, *baw, *b1w;
    cudaGetSymbolAddress((void**)&gv, g_v);
    cudaGetSymbolAddress((void**)&ga, g_a);
    cudaGetSymbolAddress((void**)&gpart, g_part);
    cudaGetSymbolAddress((void**)&vh, g_Vh);
    cudaGetSymbolAddress((void**)&ah, g_Ah);
    cudaGetSymbolAddress((void**)&xh, g_Xh);
    cudaGetSymbolAddress((void**)&bvw, g_Bv);
    cudaGetSymbolAddress((void**)&baw, g_Ba);
    cudaGetSymbolAddress((void**)&b1w, g_B1);

    cudaFuncSetAttribute(proj_gemm, cudaFuncAttributeMaxDynamicSharedMemorySize, GSM_TOTAL);
    cudaFuncSetAttribute(mlp_gemm,  cudaFuncAttributeMaxDynamicSharedMemorySize, GSM_TOTAL);

    // single prep launch: both activation converts + all 3 weight transposes
    prep_kernel<<<NB_TOTAL, 256>>>((const float4*)video, (const float4*)audio,
                                   Wv, Wa, W1, vh, ah, bvw, baw, b1w);

    // merged projections (z=0 video, z=1 audio)
    proj_gemm<<<dim3(DMc / 128, MROWS / 128, 2), 256, GSM_TOTAL>>>(
        vh, bvw, bv, gv, ah, baw, ba, ga);

    // layernorms (warp-per-row, both tensors in one launch)
    ln8_kernel<<<dim3(MROWS / 8, 2), 256>>>();

    // fused shift + context + l2norm + X build (warp per row)
    shiftx_kernel<<<MROWS / 8, 256>>>(theta);

    // gate MLP with fused gelu + W2 reduction
    mlp_gemm<<<dim3(HIDc / 128, MROWS / 128), 256, GSM_TOTAL>>>(
        xh, b1w, b1, W2, gpart);

    final_kernel<<<MROWS / 8, 256>>>(b2, out);
}